// round 11
// baseline (speedup 1.0000x reference)
#include <cuda_runtime.h>
#include <cuda_bf16.h>
#include <math.h>
#include <stdint.h>

#define NN 50000
#define EE 500000
#define ESLN 550000   // EE + NN (edges with self loops)
#define FIN 128
#define HC 256
#define CH 128
#define NCLASS 10
#define NB0 49        // ceil(NN/1024)

// ---------------- scratch (static __device__ globals; no allocation) -------
__device__ int   g_src[ESLN];
__device__ int   g_dst[ESLN];
__device__ int   g_cnt[NN];
__device__ int   g_cursor[NN];
__device__ int   g_rowptr1[NN + 1];
__device__ int   g_perm1[ESLN];
__device__ float g_XLR[(size_t)NN * 512];   // [N,512]: 0..255 = xl, 256..511 = xr
__device__ __nv_bfloat16 g_Ahi[(size_t)NN * HC];
__device__ __nv_bfloat16 g_Alo[(size_t)NN * HC];
__device__ __nv_bfloat16 g_Whi[640 * 512];  // layer0 rows 0-127, l1 128-383, l2 384-639
__device__ __nv_bfloat16 g_Wlo[640 * 512];
__device__ float g_partial[256];
__device__ float g_wmean;
__device__ int   g_bsum[64];

// ---------------- small utility kernels ------------------------------------
__global__ void zero_int_kernel(int* p, int n) {
    int i = blockIdx.x * blockDim.x + threadIdx.x;
    if (i < n) p[i] = 0;
}

// out[i] = fcb[i % NCLASS]  (classifier bias pre-fill; partials atomicAdd on top)
__global__ void out_init_kernel(float* __restrict__ out, const float* __restrict__ fcb) {
    int i = blockIdx.x * blockDim.x + threadIdx.x;
    if (i < NN * NCLASS) out[i] = fcb[i % NCLASS];
}

// edge decode (int32/int64 robust) + self loops + dst histogram (fused).
__global__ void convert_edges_hist_kernel(const unsigned int* __restrict__ ei,
                                          int* __restrict__ src, int* __restrict__ dst,
                                          int* __restrict__ cnt) {
    __shared__ int s_is64;
    if (threadIdx.x == 0) {
        unsigned int acc = 0;
#pragma unroll
        for (int k = 0; k < 32; k++) acc |= ei[2 * k + 1];
        s_is64 = (acc == 0u) ? 1 : 0;
    }
    __syncthreads();
    int is64 = s_is64;
    int i = blockIdx.x * blockDim.x + threadIdx.x;
    if (i >= ESLN) return;
    int s, d;
    if (i < EE) {
        if (is64) {
            const long long* p = reinterpret_cast<const long long*>(ei);
            s = (int)p[i];
            d = (int)p[EE + i];
        } else {
            const int* p = reinterpret_cast<const int*>(ei);
            s = p[i];
            d = p[EE + i];
        }
    } else {
        s = d = i - EE;
    }
    src[i] = s;
    dst[i] = d;
    atomicAdd(&cnt[d], 1);
}

__global__ void mean_partial_kernel(const float* __restrict__ w) {
    __shared__ float s[256];
    float acc = 0.f;
    for (int i = blockIdx.x * 256 + threadIdx.x; i < EE; i += 256 * 256) acc += w[i];
    s[threadIdx.x] = acc;
    __syncthreads();
    for (int off = 128; off > 0; off >>= 1) {
        if (threadIdx.x < off) s[threadIdx.x] += s[threadIdx.x + off];
        __syncthreads();
    }
    if (threadIdx.x == 0) g_partial[blockIdx.x] = s[0];
}

__global__ void mean_final_kernel() {
    __shared__ float s[256];
    s[threadIdx.x] = g_partial[threadIdx.x];
    __syncthreads();
    for (int off = 128; off > 0; off >>= 1) {
        if (threadIdx.x < off) s[threadIdx.x] += s[threadIdx.x + off];
        __syncthreads();
    }
    if (threadIdx.x == 0) g_wmean = s[0] / (float)EE;
}

// ---- 3-phase scan ----
__global__ void scan_local_kernel(const int* __restrict__ cnt, int* __restrict__ rowptr) {
    __shared__ int s[1024];
    int t = threadIdx.x;
    int i = blockIdx.x * 1024 + t;
    int v = (i < NN) ? cnt[i] : 0;
    s[t] = v;
    __syncthreads();
    for (int off = 1; off < 1024; off <<= 1) {
        int x = s[t];
        int y = (t >= off) ? s[t - off] : 0;
        __syncthreads();
        s[t] = x + y;
        __syncthreads();
    }
    if (i < NN) rowptr[i] = s[t] - v;
    if (t == 1023) g_bsum[blockIdx.x] = s[1023];
}

__global__ void scan_bsum_kernel(int* __restrict__ rowptr) {
    __shared__ int s[64];
    int t = threadIdx.x;
    int v = (t < NB0) ? g_bsum[t] : 0;
    s[t] = v;
    __syncthreads();
    for (int off = 1; off < 64; off <<= 1) {
        int x = s[t];
        int y = (t >= off) ? s[t - off] : 0;
        __syncthreads();
        s[t] = x + y;
        __syncthreads();
    }
    if (t < NB0) g_bsum[t] = s[t] - v;
    if (t == 63) rowptr[NN] = s[63];
}

__global__ void scan_add_kernel(int* __restrict__ rowptr, int* __restrict__ cursor) {
    int i = blockIdx.x * 1024 + threadIdx.x;
    if (i < NN) {
        int r = rowptr[i] + g_bsum[blockIdx.x];
        rowptr[i] = r;
        cursor[i] = r;
    }
}

__global__ void scatter_kernel(const int* __restrict__ dst, int* __restrict__ cursor,
                               int* __restrict__ perm, int count) {
    int e = blockIdx.x * blockDim.x + threadIdx.x;
    if (e < count) {
        int p = atomicAdd(&cursor[dst[e]], 1);
        perm[p] = e;
    }
}

// ---------------- bf16 helpers ----------------------------------------------
__device__ __forceinline__ uint32_t pack_bf16(__nv_bfloat16 a, __nv_bfloat16 b) {
    __nv_bfloat162 t = __halves2bfloat162(a, b);
    return *reinterpret_cast<uint32_t*>(&t);
}

__device__ __forceinline__ void split_bf16(float x, __nv_bfloat16& h, __nv_bfloat16& l) {
    h = __float2bfloat16_rn(x);
    l = __float2bfloat16_rn(x - __bfloat162float(h));
}

__device__ __forceinline__ void mma_bf16(float* c, const uint32_t* a, uint32_t b0, uint32_t b1) {
    asm volatile(
        "mma.sync.aligned.m16n8k16.row.col.f32.bf16.bf16.f32 "
        "{%0,%1,%2,%3}, {%4,%5,%6,%7}, {%8,%9}, {%0,%1,%2,%3};"
        : "+f"(c[0]), "+f"(c[1]), "+f"(c[2]), "+f"(c[3])
        : "r"(a[0]), "r"(a[1]), "r"(a[2]), "r"(a[3]), "r"(b0), "r"(b1));
}

__device__ __forceinline__ void ldsm_x4(uint32_t* r, uint32_t saddr) {
    asm volatile("ldmatrix.sync.aligned.m8n8.x4.shared.b16 {%0,%1,%2,%3}, [%4];"
                 : "=r"(r[0]), "=r"(r[1]), "=r"(r[2]), "=r"(r[3]) : "r"(saddr));
}

__device__ __forceinline__ void ldsm_x4_t(uint32_t* r, uint32_t saddr) {
    asm volatile("ldmatrix.sync.aligned.m8n8.x4.trans.shared.b16 {%0,%1,%2,%3}, [%4];"
                 : "=r"(r[0]), "=r"(r[1]), "=r"(r[2]), "=r"(r[3]) : "r"(saddr));
}

__device__ __forceinline__ void cp_async16(uint32_t saddr, const void* g, int sz) {
    asm volatile("cp.async.cg.shared.global [%0], [%1], 16, %2;"
                 :: "r"(saddr), "l"(g), "r"(sz));
}

// ---------------- conversion kernels ----------------------------------------
__global__ void a_convert_kernel(const float* __restrict__ A,
                                 __nv_bfloat16* __restrict__ hi,
                                 __nv_bfloat16* __restrict__ lo, int total) {
    int i = (blockIdx.x * blockDim.x + threadIdx.x) * 4;
    if (i >= total) return;
    float4 v = *reinterpret_cast<const float4*>(A + i);
    __nv_bfloat16 h0, h1, h2, h3, l0, l1, l2, l3;
    split_bf16(v.x, h0, l0); split_bf16(v.y, h1, l1);
    split_bf16(v.z, h2, l2); split_bf16(v.w, h3, l3);
    *reinterpret_cast<uint2*>(hi + i) = make_uint2(pack_bf16(h0, h1), pack_bf16(h2, h3));
    *reinterpret_cast<uint2*>(lo + i) = make_uint2(pack_bf16(l0, l1), pack_bf16(l2, l3));
}

__global__ void w_convert_kernel(const float* __restrict__ Wl0, const float* __restrict__ Wr0,
                                 const float* __restrict__ Wl1, const float* __restrict__ Wr1,
                                 const float* __restrict__ Wl2, const float* __restrict__ Wr2) {
    int i = blockIdx.x * blockDim.x + threadIdx.x;
    if (i >= 640 * 512) return;
    int row = i >> 9, col = i & 511;
    const float *Wl, *Wr;
    int k;
    if (row < 128) { Wl = Wl0; Wr = Wr0; k = row; }
    else if (row < 384) { Wl = Wl1; Wr = Wr1; k = row - 128; }
    else { Wl = Wl2; Wr = Wr2; k = row - 384; }
    float v = (col < 256) ? Wl[k * 256 + col] : Wr[k * 256 + col - 256];
    __nv_bfloat16 h, l;
    split_bf16(v, h, l);
    g_Whi[i] = h;
    g_Wlo[i] = l;
}

// ---------------- GEMM: C[N,512] = A[N,K] @ W + bias -----------------------
// (unchanged: 3xBF16 hi/lo, cp.async+ldmatrix, issue-floor bound)
__global__ __launch_bounds__(256, 2) void gemm_bf16_ldsm_kernel(
    const __nv_bfloat16* __restrict__ Ahi, const __nv_bfloat16* __restrict__ Alo,
    int Mrows, int K,
    const __nv_bfloat16* __restrict__ Whi, const __nv_bfloat16* __restrict__ Wlo,
    const float* __restrict__ blv, const float* __restrict__ brv,
    float* __restrict__ Cmat) {
    extern __shared__ uint8_t smem[];
    uint32_t sbase = (uint32_t)__cvta_generic_to_shared(smem);
    const int bcol = blockIdx.x * 128;
    const int brow = blockIdx.y * 128;
    const int tid = threadIdx.x;
    const int lane = tid & 31;
    const int warp = tid >> 5;
    const int wm = warp >> 2;
    const int wn = warp & 3;

    float acc[4][4][4];
#pragma unroll
    for (int i = 0; i < 4; i++)
#pragma unroll
        for (int j = 0; j < 4; j++)
#pragma unroll
            for (int r = 0; r < 4; r++) acc[i][j][r] = 0.f;

    auto prefetch = [&](int kt, int soff) {
#pragma unroll
        for (int i = 0; i < 2; i++) {
            int c = tid + i * 256;
            int m = c >> 2, kc = c & 3;
            int grow = brow + m;
            int sz = (grow < Mrows) ? 16 : 0;
            uint32_t da = sbase + soff + (m * 4 + (kc ^ ((m >> 1) & 3))) * 16;
            size_t gofs = (size_t)grow * K + kt + kc * 8;
            cp_async16(da, Ahi + gofs, sz);
            cp_async16(da + 8192, Alo + gofs, sz);
        }
#pragma unroll
        for (int i = 0; i < 2; i++) {
            int c = tid + i * 256;
            int k = c >> 4, nc = c & 15;
            uint32_t db = sbase + soff + 16384 + (k * 16 + (nc ^ (k & 7))) * 16;
            size_t gofs = (size_t)(kt + k) * 512 + bcol + nc * 8;
            cp_async16(db, Whi + gofs, 16);
            cp_async16(db + 8192, Wlo + gofs, 16);
        }
        asm volatile("cp.async.commit_group;");
    };

    const int nk = K >> 5;
    prefetch(0, 0);
    asm volatile("cp.async.wait_group 0;");
    __syncthreads();

    const int lr = lane & 7;
    const int sel = lane >> 3;
    int buf = 0;
    for (int it = 0; it < nk; it++) {
        if (it + 1 < nk) prefetch((it + 1) << 5, (buf ^ 1) * 32768);
        int soff = buf * 32768;
#pragma unroll
        for (int s = 0; s < 2; s++) {
            uint32_t afrag[4][4], bfrag[2][4], b2frag[2][4];
#pragma unroll
            for (int t = 0; t < 4; t++) {
                int m = wm * 64 + t * 16 + lr + ((sel & 1) << 3);
                int kc = s * 2 + ((sel >> 1) & 1);
                uint32_t addr = sbase + soff + (m * 4 + (kc ^ ((m >> 1) & 3))) * 16;
                ldsm_x4(afrag[t], addr);
            }
#pragma unroll
            for (int j2 = 0; j2 < 2; j2++) {
                int k = s * 16 + ((sel & 1) << 3) + lr;
                int nt = wn * 4 + 2 * j2 + ((sel >> 1) & 1);
                uint32_t addr = sbase + soff + 16384 + (k * 16 + (nt ^ (k & 7))) * 16;
                ldsm_x4_t(bfrag[j2], addr);
            }
#pragma unroll
            for (int i = 0; i < 4; i++)
#pragma unroll
                for (int j = 0; j < 4; j++) {
                    const uint32_t* bp = &bfrag[j >> 1][(j & 1) * 2];
                    mma_bf16(acc[i][j], afrag[i], bp[0], bp[1]);
                }
#pragma unroll
            for (int j2 = 0; j2 < 2; j2++) {
                int k = s * 16 + ((sel & 1) << 3) + lr;
                int nt = wn * 4 + 2 * j2 + ((sel >> 1) & 1);
                uint32_t addr = sbase + soff + 16384 + (k * 16 + (nt ^ (k & 7))) * 16;
                ldsm_x4_t(b2frag[j2], addr + 8192);
            }
#pragma unroll
            for (int i = 0; i < 4; i++)
#pragma unroll
                for (int j = 0; j < 4; j++) {
                    const uint32_t* bp = &b2frag[j >> 1][(j & 1) * 2];
                    mma_bf16(acc[i][j], afrag[i], bp[0], bp[1]);
                }
#pragma unroll
            for (int t = 0; t < 4; t++) {
                int m = wm * 64 + t * 16 + lr + ((sel & 1) << 3);
                int kc = s * 2 + ((sel >> 1) & 1);
                uint32_t addr = sbase + soff + (m * 4 + (kc ^ ((m >> 1) & 3))) * 16;
                ldsm_x4(afrag[t], addr + 8192);
            }
#pragma unroll
            for (int i = 0; i < 4; i++)
#pragma unroll
                for (int j = 0; j < 4; j++) {
                    const uint32_t* bp = &bfrag[j >> 1][(j & 1) * 2];
                    mma_bf16(acc[i][j], afrag[i], bp[0], bp[1]);
                }
        }
        if (it + 1 < nk) asm volatile("cp.async.wait_group 0;");
        __syncthreads();
        buf ^= 1;
    }

    int r0 = lane >> 2;
    int c0 = (lane & 3) * 2;
#pragma unroll
    for (int j = 0; j < 4; j++) {
        int gcol = bcol + wn * 32 + j * 8 + c0;
        float b0v = (gcol < 256) ? blv[gcol] : brv[gcol - 256];
        float b1v = (gcol < 256) ? blv[gcol + 1] : brv[gcol + 1 - 256];
#pragma unroll
        for (int i = 0; i < 4; i++) {
            int grow = brow + wm * 64 + i * 16 + r0;
            if (grow < Mrows) {
                float2 v = make_float2(acc[i][j][0] + b0v, acc[i][j][1] + b1v);
                *reinterpret_cast<float2*>(Cmat + (size_t)grow * 512 + gcol) = v;
            }
            if (grow + 8 < Mrows) {
                float2 v = make_float2(acc[i][j][2] + b0v, acc[i][j][3] + b1v);
                *reinterpret_cast<float2*>(Cmat + (size_t)(grow + 8) * 512 + gcol) = v;
            }
        }
    }
}

// ---------------- fused GATv2 node kernel (warp per node-head, unroll x4) ---
// Last layer (fcW != null): per-head partial classifier dot-products are
// shfl-reduced and atomically added into out (pre-filled with fcb).
__global__ __launch_bounds__(256) void gat_node_kernel(
    const float* __restrict__ XLR,
    const int* __restrict__ rowptr, const int* __restrict__ perm,
    const int* __restrict__ src, const float* __restrict__ wgt,
    const float* __restrict__ att, const float* __restrict__ We,
    const float* __restrict__ bias, int skipSelf,
    __nv_bfloat16* __restrict__ OutHi, __nv_bfloat16* __restrict__ OutLo,
    const float* __restrict__ fcW, float* __restrict__ out) {
    int wid = (blockIdx.x * blockDim.x + threadIdx.x) >> 5;
    if (wid >= NN * 2) return;
    int lane = threadIdx.x & 31;
    int node = wid >> 1;
    int h = wid & 1;
    int base = h * CH + lane * 4;
    const float4 xr = *reinterpret_cast<const float4*>(XLR + (size_t)node * 512 + 256 + base);
    const float4 av = *reinterpret_cast<const float4*>(att + base);
    const float4 wv = *reinterpret_cast<const float4*>(We + base);
    float d = 0.f;
    float4 acc = make_float4(0.f, 0.f, 0.f, 0.f);
    int i0 = rowptr[node], i1 = rowptr[node + 1];
    float wmean = g_wmean;
    int idx = i0;
#define EDGE_BODY(eV, peV)                                                     \
    {                                                                          \
        int s_ = src[eV];                                                      \
        float ea_ = (eV < EE) ? __ldg(wgt + eV) : wmean;                       \
        float4 xl_ = *reinterpret_cast<const float4*>(XLR + (size_t)s_ * 512 + base); \
        float q0 = xl_.x + xr.x + ea_ * wv.x;                                  \
        float q1 = xl_.y + xr.y + ea_ * wv.y;                                  \
        float q2 = xl_.z + xr.z + ea_ * wv.z;                                  \
        float q3 = xl_.w + xr.w + ea_ * wv.w;                                  \
        q0 = q0 > 0.f ? q0 : 0.2f * q0;                                        \
        q1 = q1 > 0.f ? q1 : 0.2f * q1;                                        \
        q2 = q2 > 0.f ? q2 : 0.2f * q2;                                        \
        q3 = q3 > 0.f ? q3 : 0.2f * q3;                                        \
        peV = q0 * av.x + q1 * av.y + q2 * av.z + q3 * av.w;                   \
        xsave = xl_;                                                           \
    }
    for (; idx + 4 <= i1; idx += 4) {
        int e0 = perm[idx], e1 = perm[idx + 1], e2 = perm[idx + 2], e3 = perm[idx + 3];
        float p0, p1, p2, p3;
        float4 xsave;
        float4 x0, x1, x2, x3;
        EDGE_BODY(e0, p0); x0 = xsave;
        EDGE_BODY(e1, p1); x1 = xsave;
        EDGE_BODY(e2, p2); x2 = xsave;
        EDGE_BODY(e3, p3); x3 = xsave;
#pragma unroll
        for (int off = 16; off >= 1; off >>= 1) {
            p0 += __shfl_xor_sync(0xffffffffu, p0, off);
            p1 += __shfl_xor_sync(0xffffffffu, p1, off);
            p2 += __shfl_xor_sync(0xffffffffu, p2, off);
            p3 += __shfl_xor_sync(0xffffffffu, p3, off);
        }
        float m0 = (skipSelf && e0 >= EE) ? 0.f : 1.f;
        float m1 = (skipSelf && e1 >= EE) ? 0.f : 1.f;
        float m2 = (skipSelf && e2 >= EE) ? 0.f : 1.f;
        float m3 = (skipSelf && e3 >= EE) ? 0.f : 1.f;
        float pe0 = __expf(p0) * m0, pe1 = __expf(p1) * m1;
        float pe2 = __expf(p2) * m2, pe3 = __expf(p3) * m3;
        d += (pe0 + pe1) + (pe2 + pe3);
        acc.x += pe0 * x0.x + pe1 * x1.x + pe2 * x2.x + pe3 * x3.x;
        acc.y += pe0 * x0.y + pe1 * x1.y + pe2 * x2.y + pe3 * x3.y;
        acc.z += pe0 * x0.z + pe1 * x1.z + pe2 * x2.z + pe3 * x3.z;
        acc.w += pe0 * x0.w + pe1 * x1.w + pe2 * x2.w + pe3 * x3.w;
    }
    for (; idx < i1; idx++) {
        int e = perm[idx];
        float p;
        float4 xsave;
        EDGE_BODY(e, p);
#pragma unroll
        for (int off = 16; off >= 1; off >>= 1) p += __shfl_xor_sync(0xffffffffu, p, off);
        float m = (skipSelf && e >= EE) ? 0.f : 1.f;
        float pe = __expf(p) * m;
        d += pe;
        acc.x += pe * xsave.x;
        acc.y += pe * xsave.y;
        acc.z += pe * xsave.z;
        acc.w += pe * xsave.w;
    }
#undef EDGE_BODY
    float inv = (d > 0.f) ? 1.f / (d + 1e-16f) : 0.f;
    const float4 bv = *reinterpret_cast<const float4*>(bias + base);
    float o0 = acc.x * inv + bv.x;
    float o1 = acc.y * inv + bv.y;
    float o2 = acc.z * inv + bv.z;
    float o3 = acc.w * inv + bv.w;
    o0 = o0 > 0.f ? o0 : expm1f(o0);
    o1 = o1 > 0.f ? o1 : expm1f(o1);
    o2 = o2 > 0.f ? o2 : expm1f(o2);
    o3 = o3 > 0.f ? o3 : expm1f(o3);
    if (fcW) {
        // per-head partial classifier: 4 channels/lane -> NCLASS partials
        float ov[4] = {o0, o1, o2, o3};
        float fa[NCLASS];
#pragma unroll
        for (int k = 0; k < NCLASS; k++) fa[k] = 0.f;
#pragma unroll
        for (int j = 0; j < 4; j++) {
            const float* wr = fcW + (size_t)(base + j) * NCLASS;
#pragma unroll
            for (int k = 0; k < NCLASS; k++) fa[k] += ov[j] * __ldg(wr + k);
        }
#pragma unroll
        for (int k = 0; k < NCLASS; k++) {
#pragma unroll
            for (int off = 16; off >= 1; off >>= 1)
                fa[k] += __shfl_xor_sync(0xffffffffu, fa[k], off);
        }
        if (lane < NCLASS)
            atomicAdd(out + (size_t)node * NCLASS + lane, fa[lane]);
    } else {
        __nv_bfloat16 h0, h1, h2, h3, l0, l1, l2, l3;
        split_bf16(o0, h0, l0); split_bf16(o1, h1, l1);
        split_bf16(o2, h2, l2); split_bf16(o3, h3, l3);
        size_t ofs = (size_t)node * HC + base;
        *reinterpret_cast<uint2*>(OutHi + ofs) = make_uint2(pack_bf16(h0, h1), pack_bf16(h2, h3));
        *reinterpret_cast<uint2*>(OutLo + ofs) = make_uint2(pack_bf16(l0, l1), pack_bf16(l2, l3));
    }
}

// ---------------- launch -----------------------------------------------------
extern "C" void kernel_launch(void* const* d_in, const int* in_sizes, int n_in,
                              void* d_out, int out_size) {
    const float* x = (const float*)d_in[0];
    const void* ei = d_in[1];
    const float* wgt = (const float*)d_in[2];
    const float *Wl[3], *bl[3], *Wr[3], *br[3], *We[3], *att[3], *bb[3];
    for (int i = 0; i < 3; i++) {
        int bse = 3 + 7 * i;
        Wl[i] = (const float*)d_in[bse + 0];
        bl[i] = (const float*)d_in[bse + 1];
        Wr[i] = (const float*)d_in[bse + 2];
        br[i] = (const float*)d_in[bse + 3];
        We[i] = (const float*)d_in[bse + 4];
        att[i] = (const float*)d_in[bse + 5];
        bb[i] = (const float*)d_in[bse + 6];
    }
    const float* fcW = (const float*)d_in[24];
    const float* fcb = (const float*)d_in[25];
    float* out = (float*)d_out;

    int *psrc, *pdst, *pcnt, *pcursor, *prow1, *pperm1;
    float* pXLR;
    __nv_bfloat16 *pAhi, *pAlo, *pWhi, *pWlo;
    cudaGetSymbolAddress((void**)&psrc, g_src);
    cudaGetSymbolAddress((void**)&pdst, g_dst);
    cudaGetSymbolAddress((void**)&pcnt, g_cnt);
    cudaGetSymbolAddress((void**)&pcursor, g_cursor);
    cudaGetSymbolAddress((void**)&prow1, g_rowptr1);
    cudaGetSymbolAddress((void**)&pperm1, g_perm1);
    cudaGetSymbolAddress((void**)&pXLR, g_XLR);
    cudaGetSymbolAddress((void**)&pAhi, g_Ahi);
    cudaGetSymbolAddress((void**)&pAlo, g_Alo);
    cudaGetSymbolAddress((void**)&pWhi, g_Whi);
    cudaGetSymbolAddress((void**)&pWlo, g_Wlo);

    cudaFuncSetAttribute(gemm_bf16_ldsm_kernel,
                         cudaFuncAttributeMaxDynamicSharedMemorySize, 65536);

    // prep: zero counts, fused decode+selfloops+hist; weight mean; out = fcb
    zero_int_kernel<<<(NN + 255) / 256, 256>>>(pcnt, NN);
    convert_edges_hist_kernel<<<(ESLN + 255) / 256, 256>>>((const unsigned int*)ei,
                                                           psrc, pdst, pcnt);
    mean_partial_kernel<<<256, 256>>>(wgt);
    mean_final_kernel<<<1, 256>>>();
    out_init_kernel<<<(NN * NCLASS + 255) / 256, 256>>>(out, fcb);

    // CSR (with self loops); layer 0 masks self loops at runtime
    scan_local_kernel<<<NB0, 1024>>>(pcnt, prow1);
    scan_bsum_kernel<<<1, 64>>>(prow1);
    scan_add_kernel<<<NB0, 1024>>>(prow1, pcursor);
    scatter_kernel<<<(ESLN + 255) / 256, 256>>>(pdst, pcursor, pperm1, ESLN);

    // weights -> bf16 hi/lo; x -> bf16 hi/lo
    w_convert_kernel<<<(640 * 512 + 255) / 256, 256>>>(Wl[0], Wr[0], Wl[1], Wr[1], Wl[2], Wr[2]);
    a_convert_kernel<<<(NN * FIN / 4 + 255) / 256, 256>>>(x, pAhi, pAlo, NN * FIN);

    dim3 ggrid(4, (NN + 127) / 128);
    int node_blocks = (NN * 2 * 32 + 255) / 256;  // one warp per (node, head)

    // Layer 0 (mask self loops)
    gemm_bf16_ldsm_kernel<<<ggrid, 256, 65536>>>(pAhi, pAlo, NN, FIN,
                                                 pWhi, pWlo, bl[0], br[0], pXLR);
    gat_node_kernel<<<node_blocks, 256>>>(pXLR, prow1, pperm1, psrc, wgt,
                                          att[0], We[0], bb[0], 1,
                                          pAhi, pAlo, nullptr, nullptr);
    // Layer 1
    gemm_bf16_ldsm_kernel<<<ggrid, 256, 65536>>>(pAhi, pAlo, NN, HC,
                                                 pWhi + 128 * 512, pWlo + 128 * 512,
                                                 bl[1], br[1], pXLR);
    gat_node_kernel<<<node_blocks, 256>>>(pXLR, prow1, pperm1, psrc, wgt,
                                          att[1], We[1], bb[1], 0,
                                          pAhi, pAlo, nullptr, nullptr);
    // Layer 2 + fused classifier (partials atomically added onto fcb prefill)
    gemm_bf16_ldsm_kernel<<<ggrid, 256, 65536>>>(pAhi, pAlo, NN, HC,
                                                 pWhi + 384 * 512, pWlo + 384 * 512,
                                                 bl[2], br[2], pXLR);
    gat_node_kernel<<<node_blocks, 256>>>(pXLR, prow1, pperm1, psrc, wgt,
                                          att[2], We[2], bb[2], 0,
                                          nullptr, nullptr, fcW, out);
}

// round 13
// speedup vs baseline: 1.0338x; 1.0338x over previous
#include <cuda_runtime.h>
#include <cuda_bf16.h>
#include <math.h>
#include <stdint.h>

#define NN 50000
#define EE 500000
#define ESLN 550000   // EE + NN (edges with self loops)
#define FIN 128
#define HC 256
#define CH 128
#define NCLASS 10
#define NB0 49        // ceil(NN/1024)

// ---------------- scratch (static __device__ globals; no allocation) -------
__device__ int   g_src[ESLN];
__device__ int   g_dst[ESLN];
__device__ int   g_cnt[NN];
__device__ int   g_cursor[NN];
__device__ int   g_rowptr1[NN + 1];
__device__ int   g_perm1[ESLN];
__device__ float g_XLR[(size_t)NN * 512];   // [N,512]: 0..255 = xl, 256..511 = xr
__device__ __nv_bfloat16 g_Ahi[(size_t)NN * HC];
__device__ __nv_bfloat16 g_Alo[(size_t)NN * HC];
__device__ __nv_bfloat16 g_Whi[640 * 512];  // layer0 rows 0-127, l1 128-383, l2 384-639
__device__ __nv_bfloat16 g_Wlo[640 * 512];
__device__ float g_partial[256];
__device__ float g_wmean;
__device__ int   g_bsum[64];

// ---------------- small utility kernels ------------------------------------
__global__ void zero_int_kernel(int* p, int n) {
    int i = blockIdx.x * blockDim.x + threadIdx.x;
    if (i < n) p[i] = 0;
}

// out[node][k] = fcb[k]  (classifier bias pre-fill; partials atomicAdd on top)
__global__ void out_init_kernel(float* __restrict__ out, const float* __restrict__ fcb) {
    __shared__ float sb[NCLASS];
    if (threadIdx.x < NCLASS) sb[threadIdx.x] = fcb[threadIdx.x];
    __syncthreads();
    int node = blockIdx.x * (256 / NCLASS) + threadIdx.x / NCLASS;
    int k = threadIdx.x % NCLASS;
    if (threadIdx.x < (256 / NCLASS) * NCLASS && node < NN)
        out[(size_t)node * NCLASS + k] = sb[k];
}

// edge_index may be int32 or int64 depending on JAX x64 config.
__global__ void convert_edges_kernel(const unsigned int* __restrict__ ei,
                                     int* __restrict__ src, int* __restrict__ dst) {
    __shared__ int s_is64;
    if (threadIdx.x == 0) {
        unsigned int acc = 0;
#pragma unroll
        for (int k = 0; k < 32; k++) acc |= ei[2 * k + 1];
        s_is64 = (acc == 0u) ? 1 : 0;
    }
    __syncthreads();
    int is64 = s_is64;
    int i = blockIdx.x * blockDim.x + threadIdx.x;
    if (i >= ESLN) return;
    if (i < EE) {
        int s, d;
        if (is64) {
            const long long* p = reinterpret_cast<const long long*>(ei);
            s = (int)p[i];
            d = (int)p[EE + i];
        } else {
            const int* p = reinterpret_cast<const int*>(ei);
            s = p[i];
            d = p[EE + i];
        }
        src[i] = s;
        dst[i] = d;
    } else {
        int v = i - EE;
        src[i] = v;
        dst[i] = v;
    }
}

__global__ void mean_partial_kernel(const float* __restrict__ w) {
    __shared__ float s[256];
    float acc = 0.f;
    for (int i = blockIdx.x * 256 + threadIdx.x; i < EE; i += 256 * 256) acc += w[i];
    s[threadIdx.x] = acc;
    __syncthreads();
    for (int off = 128; off > 0; off >>= 1) {
        if (threadIdx.x < off) s[threadIdx.x] += s[threadIdx.x + off];
        __syncthreads();
    }
    if (threadIdx.x == 0) g_partial[blockIdx.x] = s[0];
}

__global__ void mean_final_kernel() {
    __shared__ float s[256];
    s[threadIdx.x] = g_partial[threadIdx.x];
    __syncthreads();
    for (int off = 128; off > 0; off >>= 1) {
        if (threadIdx.x < off) s[threadIdx.x] += s[threadIdx.x + off];
        __syncthreads();
    }
    if (threadIdx.x == 0) g_wmean = s[0] / (float)EE;
}

__global__ void hist_kernel(const int* __restrict__ dst, int* __restrict__ cnt, int count) {
    int e = blockIdx.x * blockDim.x + threadIdx.x;
    if (e < count) atomicAdd(&cnt[dst[e]], 1);
}

// ---- 3-phase scan ----
__global__ void scan_local_kernel(const int* __restrict__ cnt, int* __restrict__ rowptr) {
    __shared__ int s[1024];
    int t = threadIdx.x;
    int i = blockIdx.x * 1024 + t;
    int v = (i < NN) ? cnt[i] : 0;
    s[t] = v;
    __syncthreads();
    for (int off = 1; off < 1024; off <<= 1) {
        int x = s[t];
        int y = (t >= off) ? s[t - off] : 0;
        __syncthreads();
        s[t] = x + y;
        __syncthreads();
    }
    if (i < NN) rowptr[i] = s[t] - v;
    if (t == 1023) g_bsum[blockIdx.x] = s[1023];
}

__global__ void scan_bsum_kernel(int* __restrict__ rowptr) {
    __shared__ int s[64];
    int t = threadIdx.x;
    int v = (t < NB0) ? g_bsum[t] : 0;
    s[t] = v;
    __syncthreads();
    for (int off = 1; off < 64; off <<= 1) {
        int x = s[t];
        int y = (t >= off) ? s[t - off] : 0;
        __syncthreads();
        s[t] = x + y;
        __syncthreads();
    }
    if (t < NB0) g_bsum[t] = s[t] - v;
    if (t == 63) rowptr[NN] = s[63];
}

__global__ void scan_add_kernel(int* __restrict__ rowptr, int* __restrict__ cursor) {
    int i = blockIdx.x * 1024 + threadIdx.x;
    if (i < NN) {
        int r = rowptr[i] + g_bsum[blockIdx.x];
        rowptr[i] = r;
        cursor[i] = r;
    }
}

__global__ void scatter_kernel(const int* __restrict__ dst, int* __restrict__ cursor,
                               int* __restrict__ perm, int count) {
    int e = blockIdx.x * blockDim.x + threadIdx.x;
    if (e < count) {
        int p = atomicAdd(&cursor[dst[e]], 1);
        perm[p] = e;
    }
}

// ---------------- bf16 helpers ----------------------------------------------
__device__ __forceinline__ uint32_t pack_bf16(__nv_bfloat16 a, __nv_bfloat16 b) {
    __nv_bfloat162 t = __halves2bfloat162(a, b);
    return *reinterpret_cast<uint32_t*>(&t);
}

__device__ __forceinline__ void split_bf16(float x, __nv_bfloat16& h, __nv_bfloat16& l) {
    h = __float2bfloat16_rn(x);
    l = __float2bfloat16_rn(x - __bfloat162float(h));
}

__device__ __forceinline__ void mma_bf16(float* c, const uint32_t* a, uint32_t b0, uint32_t b1) {
    asm volatile(
        "mma.sync.aligned.m16n8k16.row.col.f32.bf16.bf16.f32 "
        "{%0,%1,%2,%3}, {%4,%5,%6,%7}, {%8,%9}, {%0,%1,%2,%3};"
        : "+f"(c[0]), "+f"(c[1]), "+f"(c[2]), "+f"(c[3])
        : "r"(a[0]), "r"(a[1]), "r"(a[2]), "r"(a[3]), "r"(b0), "r"(b1));
}

__device__ __forceinline__ void ldsm_x4(uint32_t* r, uint32_t saddr) {
    asm volatile("ldmatrix.sync.aligned.m8n8.x4.shared.b16 {%0,%1,%2,%3}, [%4];"
                 : "=r"(r[0]), "=r"(r[1]), "=r"(r[2]), "=r"(r[3]) : "r"(saddr));
}

__device__ __forceinline__ void ldsm_x4_t(uint32_t* r, uint32_t saddr) {
    asm volatile("ldmatrix.sync.aligned.m8n8.x4.trans.shared.b16 {%0,%1,%2,%3}, [%4];"
                 : "=r"(r[0]), "=r"(r[1]), "=r"(r[2]), "=r"(r[3]) : "r"(saddr));
}

__device__ __forceinline__ void cp_async16(uint32_t saddr, const void* g, int sz) {
    asm volatile("cp.async.cg.shared.global [%0], [%1], 16, %2;"
                 :: "r"(saddr), "l"(g), "r"(sz));
}

// ---------------- conversion kernels ----------------------------------------
__global__ void a_convert_kernel(const float* __restrict__ A,
                                 __nv_bfloat16* __restrict__ hi,
                                 __nv_bfloat16* __restrict__ lo, int total) {
    int i = (blockIdx.x * blockDim.x + threadIdx.x) * 4;
    if (i >= total) return;
    float4 v = *reinterpret_cast<const float4*>(A + i);
    __nv_bfloat16 h0, h1, h2, h3, l0, l1, l2, l3;
    split_bf16(v.x, h0, l0); split_bf16(v.y, h1, l1);
    split_bf16(v.z, h2, l2); split_bf16(v.w, h3, l3);
    *reinterpret_cast<uint2*>(hi + i) = make_uint2(pack_bf16(h0, h1), pack_bf16(h2, h3));
    *reinterpret_cast<uint2*>(lo + i) = make_uint2(pack_bf16(l0, l1), pack_bf16(l2, l3));
}

__global__ void w_convert_kernel(const float* __restrict__ Wl0, const float* __restrict__ Wr0,
                                 const float* __restrict__ Wl1, const float* __restrict__ Wr1,
                                 const float* __restrict__ Wl2, const float* __restrict__ Wr2) {
    int i = blockIdx.x * blockDim.x + threadIdx.x;
    if (i >= 640 * 512) return;
    int row = i >> 9, col = i & 511;
    const float *Wl, *Wr;
    int k;
    if (row < 128) { Wl = Wl0; Wr = Wr0; k = row; }
    else if (row < 384) { Wl = Wl1; Wr = Wr1; k = row - 128; }
    else { Wl = Wl2; Wr = Wr2; k = row - 384; }
    float v = (col < 256) ? Wl[k * 256 + col] : Wr[k * 256 + col - 256];
    __nv_bfloat16 h, l;
    split_bf16(v, h, l);
    g_Whi[i] = h;
    g_Wlo[i] = l;
}

// ---------------- GEMM: C[N,512] = A[N,K] @ W + bias -----------------------
__global__ __launch_bounds__(256, 2) void gemm_bf16_ldsm_kernel(
    const __nv_bfloat16* __restrict__ Ahi, const __nv_bfloat16* __restrict__ Alo,
    int Mrows, int K,
    const __nv_bfloat16* __restrict__ Whi, const __nv_bfloat16* __restrict__ Wlo,
    const float* __restrict__ blv, const float* __restrict__ brv,
    float* __restrict__ Cmat) {
    extern __shared__ uint8_t smem[];
    uint32_t sbase = (uint32_t)__cvta_generic_to_shared(smem);
    const int bcol = blockIdx.x * 128;
    const int brow = blockIdx.y * 128;
    const int tid = threadIdx.x;
    const int lane = tid & 31;
    const int warp = tid >> 5;
    const int wm = warp >> 2;
    const int wn = warp & 3;

    float acc[4][4][4];
#pragma unroll
    for (int i = 0; i < 4; i++)
#pragma unroll
        for (int j = 0; j < 4; j++)
#pragma unroll
            for (int r = 0; r < 4; r++) acc[i][j][r] = 0.f;

    auto prefetch = [&](int kt, int soff) {
#pragma unroll
        for (int i = 0; i < 2; i++) {
            int c = tid + i * 256;
            int m = c >> 2, kc = c & 3;
            int grow = brow + m;
            int sz = (grow < Mrows) ? 16 : 0;
            uint32_t da = sbase + soff + (m * 4 + (kc ^ ((m >> 1) & 3))) * 16;
            size_t gofs = (size_t)grow * K + kt + kc * 8;
            cp_async16(da, Ahi + gofs, sz);
            cp_async16(da + 8192, Alo + gofs, sz);
        }
#pragma unroll
        for (int i = 0; i < 2; i++) {
            int c = tid + i * 256;
            int k = c >> 4, nc = c & 15;
            uint32_t db = sbase + soff + 16384 + (k * 16 + (nc ^ (k & 7))) * 16;
            size_t gofs = (size_t)(kt + k) * 512 + bcol + nc * 8;
            cp_async16(db, Whi + gofs, 16);
            cp_async16(db + 8192, Wlo + gofs, 16);
        }
        asm volatile("cp.async.commit_group;");
    };

    const int nk = K >> 5;
    prefetch(0, 0);
    asm volatile("cp.async.wait_group 0;");
    __syncthreads();

    const int lr = lane & 7;
    const int sel = lane >> 3;
    int buf = 0;
    for (int it = 0; it < nk; it++) {
        if (it + 1 < nk) prefetch((it + 1) << 5, (buf ^ 1) * 32768);
        int soff = buf * 32768;
#pragma unroll
        for (int s = 0; s < 2; s++) {
            uint32_t afrag[4][4], bfrag[2][4], b2frag[2][4];
#pragma unroll
            for (int t = 0; t < 4; t++) {
                int m = wm * 64 + t * 16 + lr + ((sel & 1) << 3);
                int kc = s * 2 + ((sel >> 1) & 1);
                uint32_t addr = sbase + soff + (m * 4 + (kc ^ ((m >> 1) & 3))) * 16;
                ldsm_x4(afrag[t], addr);
            }
#pragma unroll
            for (int j2 = 0; j2 < 2; j2++) {
                int k = s * 16 + ((sel & 1) << 3) + lr;
                int nt = wn * 4 + 2 * j2 + ((sel >> 1) & 1);
                uint32_t addr = sbase + soff + 16384 + (k * 16 + (nt ^ (k & 7))) * 16;
                ldsm_x4_t(bfrag[j2], addr);
            }
#pragma unroll
            for (int i = 0; i < 4; i++)
#pragma unroll
                for (int j = 0; j < 4; j++) {
                    const uint32_t* bp = &bfrag[j >> 1][(j & 1) * 2];
                    mma_bf16(acc[i][j], afrag[i], bp[0], bp[1]);
                }
#pragma unroll
            for (int j2 = 0; j2 < 2; j2++) {
                int k = s * 16 + ((sel & 1) << 3) + lr;
                int nt = wn * 4 + 2 * j2 + ((sel >> 1) & 1);
                uint32_t addr = sbase + soff + 16384 + (k * 16 + (nt ^ (k & 7))) * 16;
                ldsm_x4_t(b2frag[j2], addr + 8192);
            }
#pragma unroll
            for (int i = 0; i < 4; i++)
#pragma unroll
                for (int j = 0; j < 4; j++) {
                    const uint32_t* bp = &b2frag[j >> 1][(j & 1) * 2];
                    mma_bf16(acc[i][j], afrag[i], bp[0], bp[1]);
                }
#pragma unroll
            for (int t = 0; t < 4; t++) {
                int m = wm * 64 + t * 16 + lr + ((sel & 1) << 3);
                int kc = s * 2 + ((sel >> 1) & 1);
                uint32_t addr = sbase + soff + (m * 4 + (kc ^ ((m >> 1) & 3))) * 16;
                ldsm_x4(afrag[t], addr + 8192);
            }
#pragma unroll
            for (int i = 0; i < 4; i++)
#pragma unroll
                for (int j = 0; j < 4; j++) {
                    const uint32_t* bp = &bfrag[j >> 1][(j & 1) * 2];
                    mma_bf16(acc[i][j], afrag[i], bp[0], bp[1]);
                }
        }
        if (it + 1 < nk) asm volatile("cp.async.wait_group 0;");
        __syncthreads();
        buf ^= 1;
    }

    int r0 = lane >> 2;
    int c0 = (lane & 3) * 2;
#pragma unroll
    for (int j = 0; j < 4; j++) {
        int gcol = bcol + wn * 32 + j * 8 + c0;
        float b0v = (gcol < 256) ? blv[gcol] : brv[gcol - 256];
        float b1v = (gcol < 256) ? blv[gcol + 1] : brv[gcol + 1 - 256];
#pragma unroll
        for (int i = 0; i < 4; i++) {
            int grow = brow + wm * 64 + i * 16 + r0;
            if (grow < Mrows) {
                float2 v = make_float2(acc[i][j][0] + b0v, acc[i][j][1] + b1v);
                *reinterpret_cast<float2*>(Cmat + (size_t)grow * 512 + gcol) = v;
            }
            if (grow + 8 < Mrows) {
                float2 v = make_float2(acc[i][j][2] + b0v, acc[i][j][3] + b1v);
                *reinterpret_cast<float2*>(Cmat + (size_t)(grow + 8) * 512 + gcol) = v;
            }
        }
    }
}

// ---- shared edge-loop macro for the two node kernels ----
#define EDGE_BODY(eV, peV)                                                     \
    {                                                                          \
        int s_ = src[eV];                                                      \
        float ea_ = (eV < EE) ? __ldg(wgt + eV) : wmean;                       \
        float4 xl_ = *reinterpret_cast<const float4*>(XLR + (size_t)s_ * 512 + base); \
        float q0 = xl_.x + xr.x + ea_ * wv.x;                                  \
        float q1 = xl_.y + xr.y + ea_ * wv.y;                                  \
        float q2 = xl_.z + xr.z + ea_ * wv.z;                                  \
        float q3 = xl_.w + xr.w + ea_ * wv.w;                                  \
        q0 = q0 > 0.f ? q0 : 0.2f * q0;                                        \
        q1 = q1 > 0.f ? q1 : 0.2f * q1;                                        \
        q2 = q2 > 0.f ? q2 : 0.2f * q2;                                        \
        q3 = q3 > 0.f ? q3 : 0.2f * q3;                                        \
        peV = q0 * av.x + q1 * av.y + q2 * av.z + q3 * av.w;                   \
        xsave = xl_;                                                           \
    }

#define GAT_EDGE_LOOP                                                          \
    float d = 0.f;                                                             \
    float4 acc = make_float4(0.f, 0.f, 0.f, 0.f);                              \
    int i0 = rowptr[node], i1 = rowptr[node + 1];                              \
    float wmean = g_wmean;                                                     \
    int idx = i0;                                                              \
    for (; idx + 4 <= i1; idx += 4) {                                          \
        int e0 = perm[idx], e1 = perm[idx + 1], e2 = perm[idx + 2], e3 = perm[idx + 3]; \
        float p0, p1, p2, p3;                                                  \
        float4 xsave;                                                          \
        float4 x0, x1, x2, x3;                                                 \
        EDGE_BODY(e0, p0); x0 = xsave;                                         \
        EDGE_BODY(e1, p1); x1 = xsave;                                         \
        EDGE_BODY(e2, p2); x2 = xsave;                                         \
        EDGE_BODY(e3, p3); x3 = xsave;                                         \
        _Pragma("unroll")                                                      \
        for (int off = 16; off >= 1; off >>= 1) {                              \
            p0 += __shfl_xor_sync(0xffffffffu, p0, off);                       \
            p1 += __shfl_xor_sync(0xffffffffu, p1, off);                       \
            p2 += __shfl_xor_sync(0xffffffffu, p2, off);                       \
            p3 += __shfl_xor_sync(0xffffffffu, p3, off);                       \
        }                                                                      \
        float m0 = (skipSelf && e0 >= EE) ? 0.f : 1.f;                         \
        float m1 = (skipSelf && e1 >= EE) ? 0.f : 1.f;                         \
        float m2 = (skipSelf && e2 >= EE) ? 0.f : 1.f;                         \
        float m3 = (skipSelf && e3 >= EE) ? 0.f : 1.f;                         \
        float pe0 = __expf(p0) * m0, pe1 = __expf(p1) * m1;                    \
        float pe2 = __expf(p2) * m2, pe3 = __expf(p3) * m3;                    \
        d += (pe0 + pe1) + (pe2 + pe3);                                        \
        acc.x += pe0 * x0.x + pe1 * x1.x + pe2 * x2.x + pe3 * x3.x;            \
        acc.y += pe0 * x0.y + pe1 * x1.y + pe2 * x2.y + pe3 * x3.y;            \
        acc.z += pe0 * x0.z + pe1 * x1.z + pe2 * x2.z + pe3 * x3.z;            \
        acc.w += pe0 * x0.w + pe1 * x1.w + pe2 * x2.w + pe3 * x3.w;            \
    }                                                                          \
    for (; idx < i1; idx++) {                                                  \
        int e = perm[idx];                                                     \
        float p;                                                               \
        float4 xsave;                                                          \
        EDGE_BODY(e, p);                                                       \
        _Pragma("unroll")                                                      \
        for (int off = 16; off >= 1; off >>= 1)                                \
            p += __shfl_xor_sync(0xffffffffu, p, off);                         \
        float m = (skipSelf && e >= EE) ? 0.f : 1.f;                           \
        float pe = __expf(p) * m;                                              \
        d += pe;                                                               \
        acc.x += pe * xsave.x;                                                 \
        acc.y += pe * xsave.y;                                                 \
        acc.z += pe * xsave.z;                                                 \
        acc.w += pe * xsave.w;                                                 \
    }

// ---------------- fused GATv2 node kernel (layers 0/1: bf16 hi/lo out) ------
__global__ __launch_bounds__(256) void gat_node_kernel(
    const float* __restrict__ XLR,
    const int* __restrict__ rowptr, const int* __restrict__ perm,
    const int* __restrict__ src, const float* __restrict__ wgt,
    const float* __restrict__ att, const float* __restrict__ We,
    const float* __restrict__ bias, int skipSelf,
    __nv_bfloat16* __restrict__ OutHi, __nv_bfloat16* __restrict__ OutLo) {
    int wid = (blockIdx.x * blockDim.x + threadIdx.x) >> 5;
    if (wid >= NN * 2) return;
    int lane = threadIdx.x & 31;
    int node = wid >> 1;
    int h = wid & 1;
    int base = h * CH + lane * 4;
    const float4 xr = *reinterpret_cast<const float4*>(XLR + (size_t)node * 512 + 256 + base);
    const float4 av = *reinterpret_cast<const float4*>(att + base);
    const float4 wv = *reinterpret_cast<const float4*>(We + base);
    GAT_EDGE_LOOP
    float inv = (d > 0.f) ? 1.f / (d + 1e-16f) : 0.f;
    const float4 bv = *reinterpret_cast<const float4*>(bias + base);
    float o0 = acc.x * inv + bv.x;
    float o1 = acc.y * inv + bv.y;
    float o2 = acc.z * inv + bv.z;
    float o3 = acc.w * inv + bv.w;
    o0 = o0 > 0.f ? o0 : expm1f(o0);
    o1 = o1 > 0.f ? o1 : expm1f(o1);
    o2 = o2 > 0.f ? o2 : expm1f(o2);
    o3 = o3 > 0.f ? o3 : expm1f(o3);
    __nv_bfloat16 h0, h1, h2, h3, l0, l1, l2, l3;
    split_bf16(o0, h0, l0); split_bf16(o1, h1, l1);
    split_bf16(o2, h2, l2); split_bf16(o3, h3, l3);
    size_t ofs = (size_t)node * HC + base;
    *reinterpret_cast<uint2*>(OutHi + ofs) = make_uint2(pack_bf16(h0, h1), pack_bf16(h2, h3));
    *reinterpret_cast<uint2*>(OutLo + ofs) = make_uint2(pack_bf16(l0, l1), pack_bf16(l2, l3));
}

// ---------------- layer-2 node kernel with fused classifier (separate fn) ---
__global__ __launch_bounds__(256) void gat_node_fc_kernel(
    const float* __restrict__ XLR,
    const int* __restrict__ rowptr, const int* __restrict__ perm,
    const int* __restrict__ src, const float* __restrict__ wgt,
    const float* __restrict__ att, const float* __restrict__ We,
    const float* __restrict__ bias, int skipSelf,
    const float* __restrict__ fcW, float* __restrict__ out) {
    int wid = (blockIdx.x * blockDim.x + threadIdx.x) >> 5;
    if (wid >= NN * 2) return;
    int lane = threadIdx.x & 31;
    int node = wid >> 1;
    int h = wid & 1;
    int base = h * CH + lane * 4;
    const float4 xr = *reinterpret_cast<const float4*>(XLR + (size_t)node * 512 + 256 + base);
    const float4 av = *reinterpret_cast<const float4*>(att + base);
    const float4 wv = *reinterpret_cast<const float4*>(We + base);
    GAT_EDGE_LOOP
    float inv = (d > 0.f) ? 1.f / (d + 1e-16f) : 0.f;
    const float4 bv = *reinterpret_cast<const float4*>(bias + base);
    float o0 = acc.x * inv + bv.x;
    float o1 = acc.y * inv + bv.y;
    float o2 = acc.z * inv + bv.z;
    float o3 = acc.w * inv + bv.w;
    o0 = o0 > 0.f ? o0 : expm1f(o0);
    o1 = o1 > 0.f ? o1 : expm1f(o1);
    o2 = o2 > 0.f ? o2 : expm1f(o2);
    o3 = o3 > 0.f ? o3 : expm1f(o3);
    float fa[NCLASS];
    {
        const float* wr0 = fcW + (size_t)(base + 0) * NCLASS;
        const float* wr1 = fcW + (size_t)(base + 1) * NCLASS;
        const float* wr2 = fcW + (size_t)(base + 2) * NCLASS;
        const float* wr3 = fcW + (size_t)(base + 3) * NCLASS;
#pragma unroll
        for (int k = 0; k < NCLASS; k++)
            fa[k] = o0 * __ldg(wr0 + k) + o1 * __ldg(wr1 + k) +
                    o2 * __ldg(wr2 + k) + o3 * __ldg(wr3 + k);
    }
#pragma unroll
    for (int k = 0; k < NCLASS; k++) {
#pragma unroll
        for (int off = 16; off >= 1; off >>= 1)
            fa[k] += __shfl_xor_sync(0xffffffffu, fa[k], off);
    }
    if (lane < NCLASS)
        atomicAdd(out + (size_t)node * NCLASS + lane, fa[lane]);
}

#undef EDGE_BODY
#undef GAT_EDGE_LOOP

// ---------------- launch -----------------------------------------------------
extern "C" void kernel_launch(void* const* d_in, const int* in_sizes, int n_in,
                              void* d_out, int out_size) {
    const float* x = (const float*)d_in[0];
    const void* ei = d_in[1];
    const float* wgt = (const float*)d_in[2];
    const float *Wl[3], *bl[3], *Wr[3], *br[3], *We[3], *att[3], *bb[3];
    for (int i = 0; i < 3; i++) {
        int bse = 3 + 7 * i;
        Wl[i] = (const float*)d_in[bse + 0];
        bl[i] = (const float*)d_in[bse + 1];
        Wr[i] = (const float*)d_in[bse + 2];
        br[i] = (const float*)d_in[bse + 3];
        We[i] = (const float*)d_in[bse + 4];
        att[i] = (const float*)d_in[bse + 5];
        bb[i] = (const float*)d_in[bse + 6];
    }
    const float* fcW = (const float*)d_in[24];
    const float* fcb = (const float*)d_in[25];
    float* out = (float*)d_out;

    int *psrc, *pdst, *pcnt, *pcursor, *prow1, *pperm1;
    float* pXLR;
    __nv_bfloat16 *pAhi, *pAlo, *pWhi, *pWlo;
    cudaGetSymbolAddress((void**)&psrc, g_src);
    cudaGetSymbolAddress((void**)&pdst, g_dst);
    cudaGetSymbolAddress((void**)&pcnt, g_cnt);
    cudaGetSymbolAddress((void**)&pcursor, g_cursor);
    cudaGetSymbolAddress((void**)&prow1, g_rowptr1);
    cudaGetSymbolAddress((void**)&pperm1, g_perm1);
    cudaGetSymbolAddress((void**)&pXLR, g_XLR);
    cudaGetSymbolAddress((void**)&pAhi, g_Ahi);
    cudaGetSymbolAddress((void**)&pAlo, g_Alo);
    cudaGetSymbolAddress((void**)&pWhi, g_Whi);
    cudaGetSymbolAddress((void**)&pWlo, g_Wlo);

    cudaFuncSetAttribute(gemm_bf16_ldsm_kernel,
                         cudaFuncAttributeMaxDynamicSharedMemorySize, 65536);

    // prep (R9): decode+selfloops, weight mean; out prefilled with fcb
    convert_edges_kernel<<<(ESLN + 255) / 256, 256>>>((const unsigned int*)ei, psrc, pdst);
    mean_partial_kernel<<<256, 256>>>(wgt);
    mean_final_kernel<<<1, 256>>>();
    out_init_kernel<<<(NN + 24) / 25, 256>>>(out, fcb);  // 25 nodes per block

    // CSR (with self loops); layer 0 masks self loops at runtime
    zero_int_kernel<<<(NN + 255) / 256, 256>>>(pcnt, NN);
    hist_kernel<<<(ESLN + 255) / 256, 256>>>(pdst, pcnt, ESLN);
    scan_local_kernel<<<NB0, 1024>>>(pcnt, prow1);
    scan_bsum_kernel<<<1, 64>>>(prow1);
    scan_add_kernel<<<NB0, 1024>>>(prow1, pcursor);
    scatter_kernel<<<(ESLN + 255) / 256, 256>>>(pdst, pcursor, pperm1, ESLN);

    // weights -> bf16 hi/lo; x -> bf16 hi/lo
    w_convert_kernel<<<(640 * 512 + 255) / 256, 256>>>(Wl[0], Wr[0], Wl[1], Wr[1], Wl[2], Wr[2]);
    a_convert_kernel<<<(NN * FIN / 4 + 255) / 256, 256>>>(x, pAhi, pAlo, NN * FIN);

    dim3 ggrid(4, (NN + 127) / 128);
    int node_blocks = (NN * 2 * 32 + 255) / 256;  // one warp per (node, head)

    // Layer 0 (mask self loops)
    gemm_bf16_ldsm_kernel<<<ggrid, 256, 65536>>>(pAhi, pAlo, NN, FIN,
                                                 pWhi, pWlo, bl[0], br[0], pXLR);
    gat_node_kernel<<<node_blocks, 256>>>(pXLR, prow1, pperm1, psrc, wgt,
                                          att[0], We[0], bb[0], 1,
                                          pAhi, pAlo);
    // Layer 1
    gemm_bf16_ldsm_kernel<<<ggrid, 256, 65536>>>(pAhi, pAlo, NN, HC,
                                                 pWhi + 128 * 512, pWlo + 128 * 512,
                                                 bl[1], br[1], pXLR);
    gat_node_kernel<<<node_blocks, 256>>>(pXLR, prow1, pperm1, psrc, wgt,
                                          att[1], We[1], bb[1], 0,
                                          pAhi, pAlo);
    // Layer 2: separate fused-classifier kernel (register profile isolated)
    gemm_bf16_ldsm_kernel<<<ggrid, 256, 65536>>>(pAhi, pAlo, NN, HC,
                                                 pWhi + 384 * 512, pWlo + 384 * 512,
                                                 bl[2], br[2], pXLR);
    gat_node_fc_kernel<<<node_blocks, 256>>>(pXLR, prow1, pperm1, psrc, wgt,
                                             att[2], We[2], bb[2], 0,
                                             fcW, out);
}

// round 14
// speedup vs baseline: 1.1830x; 1.1444x over previous
#include <cuda_runtime.h>
#include <cuda_bf16.h>
#include <math.h>
#include <stdint.h>

#define NN 50000
#define EE 500000
#define ESLN 550000   // EE + NN (edges with self loops)
#define FIN 128
#define HC 256
#define CH 128
#define NCLASS 10
#define NB0 49        // ceil(NN/1024)

// ---------------- scratch (static __device__ globals; no allocation) -------
__device__ int   g_src[ESLN];
__device__ int   g_dst[ESLN];
__device__ int   g_cnt[NN];
__device__ int   g_cursor[NN];
__device__ int   g_rowptr1[NN + 1];
__device__ int   g_srcf[ESLN];   // per-CSR-slot: src | (selfloop << 31)
__device__ float g_ea[ESLN];     // per-CSR-slot: edge attr (wgt or wmean)
__device__ float g_XLR[(size_t)NN * 512];   // [N,512]: 0..255 = xl, 256..511 = xr
__device__ float g_HA[(size_t)NN * HC];     // final layer f32 output
__device__ __nv_bfloat16 g_Ahi[(size_t)NN * HC];
__device__ __nv_bfloat16 g_Alo[(size_t)NN * HC];
__device__ __nv_bfloat16 g_Whi[640 * 512];  // layer0 rows 0-127, l1 128-383, l2 384-639
__device__ __nv_bfloat16 g_Wlo[640 * 512];
__device__ float g_partial[256];
__device__ float g_wmean;
__device__ int   g_bsum[64];

// ---------------- small utility kernels ------------------------------------
__global__ void zero_int_kernel(int* p, int n) {
    int i = blockIdx.x * blockDim.x + threadIdx.x;
    if (i < n) p[i] = 0;
}

// edge decode (int32/int64 robust) + self loops + dst histogram (fused).
__global__ void convert_edges_hist_kernel(const unsigned int* __restrict__ ei,
                                          int* __restrict__ src, int* __restrict__ dst,
                                          int* __restrict__ cnt) {
    __shared__ int s_is64;
    if (threadIdx.x == 0) {
        unsigned int acc = 0;
#pragma unroll
        for (int k = 0; k < 32; k++) acc |= ei[2 * k + 1];
        s_is64 = (acc == 0u) ? 1 : 0;
    }
    __syncthreads();
    int is64 = s_is64;
    int i = blockIdx.x * blockDim.x + threadIdx.x;
    if (i >= ESLN) return;
    int s, d;
    if (i < EE) {
        if (is64) {
            const long long* p = reinterpret_cast<const long long*>(ei);
            s = (int)p[i];
            d = (int)p[EE + i];
        } else {
            const int* p = reinterpret_cast<const int*>(ei);
            s = p[i];
            d = p[EE + i];
        }
    } else {
        s = d = i - EE;
    }
    src[i] = s;
    dst[i] = d;
    atomicAdd(&cnt[d], 1);
}

__global__ void mean_partial_kernel(const float* __restrict__ w) {
    __shared__ float s[256];
    float acc = 0.f;
    for (int i = blockIdx.x * 256 + threadIdx.x; i < EE; i += 256 * 256) acc += w[i];
    s[threadIdx.x] = acc;
    __syncthreads();
    for (int off = 128; off > 0; off >>= 1) {
        if (threadIdx.x < off) s[threadIdx.x] += s[threadIdx.x + off];
        __syncthreads();
    }
    if (threadIdx.x == 0) g_partial[blockIdx.x] = s[0];
}

__global__ void mean_final_kernel() {
    __shared__ float s[256];
    s[threadIdx.x] = g_partial[threadIdx.x];
    __syncthreads();
    for (int off = 128; off > 0; off >>= 1) {
        if (threadIdx.x < off) s[threadIdx.x] += s[threadIdx.x + off];
        __syncthreads();
    }
    if (threadIdx.x == 0) g_wmean = s[0] / (float)EE;
}

// ---- 3-phase scan ----
__global__ void scan_local_kernel(const int* __restrict__ cnt, int* __restrict__ rowptr) {
    __shared__ int s[1024];
    int t = threadIdx.x;
    int i = blockIdx.x * 1024 + t;
    int v = (i < NN) ? cnt[i] : 0;
    s[t] = v;
    __syncthreads();
    for (int off = 1; off < 1024; off <<= 1) {
        int x = s[t];
        int y = (t >= off) ? s[t - off] : 0;
        __syncthreads();
        s[t] = x + y;
        __syncthreads();
    }
    if (i < NN) rowptr[i] = s[t] - v;
    if (t == 1023) g_bsum[blockIdx.x] = s[1023];
}

__global__ void scan_bsum_kernel(int* __restrict__ rowptr) {
    __shared__ int s[64];
    int t = threadIdx.x;
    int v = (t < NB0) ? g_bsum[t] : 0;
    s[t] = v;
    __syncthreads();
    for (int off = 1; off < 64; off <<= 1) {
        int x = s[t];
        int y = (t >= off) ? s[t - off] : 0;
        __syncthreads();
        s[t] = x + y;
        __syncthreads();
    }
    if (t < NB0) g_bsum[t] = s[t] - v;
    if (t == 63) rowptr[NN] = s[63];
}

__global__ void scan_add_kernel(int* __restrict__ rowptr, int* __restrict__ cursor) {
    int i = blockIdx.x * 1024 + threadIdx.x;
    if (i < NN) {
        int r = rowptr[i] + g_bsum[blockIdx.x];
        rowptr[i] = r;
        cursor[i] = r;
    }
}

// Scatter resolves the indirection at build time: stores src|flag and edge
// attr at the permuted slot, so the node kernels read sequentially.
__global__ void scatter_kernel(const int* __restrict__ src, const int* __restrict__ dst,
                               const float* __restrict__ wgt, int* __restrict__ cursor,
                               int* __restrict__ srcf, float* __restrict__ ea, int count) {
    int e = blockIdx.x * blockDim.x + threadIdx.x;
    if (e < count) {
        int p = atomicAdd(&cursor[dst[e]], 1);
        int flag = (e >= EE) ? (int)0x80000000 : 0;
        srcf[p] = src[e] | flag;
        ea[p] = (e < EE) ? wgt[e] : g_wmean;
    }
}

// ---------------- bf16 helpers ----------------------------------------------
__device__ __forceinline__ uint32_t pack_bf16(__nv_bfloat16 a, __nv_bfloat16 b) {
    __nv_bfloat162 t = __halves2bfloat162(a, b);
    return *reinterpret_cast<uint32_t*>(&t);
}

__device__ __forceinline__ void split_bf16(float x, __nv_bfloat16& h, __nv_bfloat16& l) {
    h = __float2bfloat16_rn(x);
    l = __float2bfloat16_rn(x - __bfloat162float(h));
}

__device__ __forceinline__ void mma_bf16(float* c, const uint32_t* a, uint32_t b0, uint32_t b1) {
    asm volatile(
        "mma.sync.aligned.m16n8k16.row.col.f32.bf16.bf16.f32 "
        "{%0,%1,%2,%3}, {%4,%5,%6,%7}, {%8,%9}, {%0,%1,%2,%3};"
        : "+f"(c[0]), "+f"(c[1]), "+f"(c[2]), "+f"(c[3])
        : "r"(a[0]), "r"(a[1]), "r"(a[2]), "r"(a[3]), "r"(b0), "r"(b1));
}

__device__ __forceinline__ void ldsm_x4(uint32_t* r, uint32_t saddr) {
    asm volatile("ldmatrix.sync.aligned.m8n8.x4.shared.b16 {%0,%1,%2,%3}, [%4];"
                 : "=r"(r[0]), "=r"(r[1]), "=r"(r[2]), "=r"(r[3]) : "r"(saddr));
}

__device__ __forceinline__ void ldsm_x4_t(uint32_t* r, uint32_t saddr) {
    asm volatile("ldmatrix.sync.aligned.m8n8.x4.trans.shared.b16 {%0,%1,%2,%3}, [%4];"
                 : "=r"(r[0]), "=r"(r[1]), "=r"(r[2]), "=r"(r[3]) : "r"(saddr));
}

__device__ __forceinline__ void cp_async16(uint32_t saddr, const void* g, int sz) {
    asm volatile("cp.async.cg.shared.global [%0], [%1], 16, %2;"
                 :: "r"(saddr), "l"(g), "r"(sz));
}

// ---------------- conversion kernels ----------------------------------------
__global__ void a_convert_kernel(const float* __restrict__ A,
                                 __nv_bfloat16* __restrict__ hi,
                                 __nv_bfloat16* __restrict__ lo, int total) {
    int i = (blockIdx.x * blockDim.x + threadIdx.x) * 4;
    if (i >= total) return;
    float4 v = *reinterpret_cast<const float4*>(A + i);
    __nv_bfloat16 h0, h1, h2, h3, l0, l1, l2, l3;
    split_bf16(v.x, h0, l0); split_bf16(v.y, h1, l1);
    split_bf16(v.z, h2, l2); split_bf16(v.w, h3, l3);
    *reinterpret_cast<uint2*>(hi + i) = make_uint2(pack_bf16(h0, h1), pack_bf16(h2, h3));
    *reinterpret_cast<uint2*>(lo + i) = make_uint2(pack_bf16(l0, l1), pack_bf16(l2, l3));
}

__global__ void w_convert_kernel(const float* __restrict__ Wl0, const float* __restrict__ Wr0,
                                 const float* __restrict__ Wl1, const float* __restrict__ Wr1,
                                 const float* __restrict__ Wl2, const float* __restrict__ Wr2) {
    int i = blockIdx.x * blockDim.x + threadIdx.x;
    if (i >= 640 * 512) return;
    int row = i >> 9, col = i & 511;
    const float *Wl, *Wr;
    int k;
    if (row < 128) { Wl = Wl0; Wr = Wr0; k = row; }
    else if (row < 384) { Wl = Wl1; Wr = Wr1; k = row - 128; }
    else { Wl = Wl2; Wr = Wr2; k = row - 384; }
    float v = (col < 256) ? Wl[k * 256 + col] : Wr[k * 256 + col - 256];
    __nv_bfloat16 h, l;
    split_bf16(v, h, l);
    g_Whi[i] = h;
    g_Wlo[i] = l;
}

// ---------------- GEMM: C[N,512] = A[N,K] @ W + bias (exact R9) -------------
__global__ __launch_bounds__(256, 2) void gemm_bf16_ldsm_kernel(
    const __nv_bfloat16* __restrict__ Ahi, const __nv_bfloat16* __restrict__ Alo,
    int Mrows, int K,
    const __nv_bfloat16* __restrict__ Whi, const __nv_bfloat16* __restrict__ Wlo,
    const float* __restrict__ blv, const float* __restrict__ brv,
    float* __restrict__ Cmat) {
    extern __shared__ uint8_t smem[];
    uint32_t sbase = (uint32_t)__cvta_generic_to_shared(smem);
    const int bcol = blockIdx.x * 128;
    const int brow = blockIdx.y * 128;
    const int tid = threadIdx.x;
    const int lane = tid & 31;
    const int warp = tid >> 5;
    const int wm = warp >> 2;
    const int wn = warp & 3;

    float acc[4][4][4];
#pragma unroll
    for (int i = 0; i < 4; i++)
#pragma unroll
        for (int j = 0; j < 4; j++)
#pragma unroll
            for (int r = 0; r < 4; r++) acc[i][j][r] = 0.f;

    auto prefetch = [&](int kt, int soff) {
#pragma unroll
        for (int i = 0; i < 2; i++) {
            int c = tid + i * 256;
            int m = c >> 2, kc = c & 3;
            int grow = brow + m;
            int sz = (grow < Mrows) ? 16 : 0;
            uint32_t da = sbase + soff + (m * 4 + (kc ^ ((m >> 1) & 3))) * 16;
            size_t gofs = (size_t)grow * K + kt + kc * 8;
            cp_async16(da, Ahi + gofs, sz);
            cp_async16(da + 8192, Alo + gofs, sz);
        }
#pragma unroll
        for (int i = 0; i < 2; i++) {
            int c = tid + i * 256;
            int k = c >> 4, nc = c & 15;
            uint32_t db = sbase + soff + 16384 + (k * 16 + (nc ^ (k & 7))) * 16;
            size_t gofs = (size_t)(kt + k) * 512 + bcol + nc * 8;
            cp_async16(db, Whi + gofs, 16);
            cp_async16(db + 8192, Wlo + gofs, 16);
        }
        asm volatile("cp.async.commit_group;");
    };

    const int nk = K >> 5;
    prefetch(0, 0);
    asm volatile("cp.async.wait_group 0;");
    __syncthreads();

    const int lr = lane & 7;
    const int sel = lane >> 3;
    int buf = 0;
    for (int it = 0; it < nk; it++) {
        if (it + 1 < nk) prefetch((it + 1) << 5, (buf ^ 1) * 32768);
        int soff = buf * 32768;
#pragma unroll
        for (int s = 0; s < 2; s++) {
            uint32_t afrag[4][4], bfrag[2][4], b2frag[2][4];
#pragma unroll
            for (int t = 0; t < 4; t++) {
                int m = wm * 64 + t * 16 + lr + ((sel & 1) << 3);
                int kc = s * 2 + ((sel >> 1) & 1);
                uint32_t addr = sbase + soff + (m * 4 + (kc ^ ((m >> 1) & 3))) * 16;
                ldsm_x4(afrag[t], addr);
            }
#pragma unroll
            for (int j2 = 0; j2 < 2; j2++) {
                int k = s * 16 + ((sel & 1) << 3) + lr;
                int nt = wn * 4 + 2 * j2 + ((sel >> 1) & 1);
                uint32_t addr = sbase + soff + 16384 + (k * 16 + (nt ^ (k & 7))) * 16;
                ldsm_x4_t(bfrag[j2], addr);
            }
#pragma unroll
            for (int i = 0; i < 4; i++)
#pragma unroll
                for (int j = 0; j < 4; j++) {
                    const uint32_t* bp = &bfrag[j >> 1][(j & 1) * 2];
                    mma_bf16(acc[i][j], afrag[i], bp[0], bp[1]);
                }
#pragma unroll
            for (int j2 = 0; j2 < 2; j2++) {
                int k = s * 16 + ((sel & 1) << 3) + lr;
                int nt = wn * 4 + 2 * j2 + ((sel >> 1) & 1);
                uint32_t addr = sbase + soff + 16384 + (k * 16 + (nt ^ (k & 7))) * 16;
                ldsm_x4_t(b2frag[j2], addr + 8192);
            }
#pragma unroll
            for (int i = 0; i < 4; i++)
#pragma unroll
                for (int j = 0; j < 4; j++) {
                    const uint32_t* bp = &b2frag[j >> 1][(j & 1) * 2];
                    mma_bf16(acc[i][j], afrag[i], bp[0], bp[1]);
                }
#pragma unroll
            for (int t = 0; t < 4; t++) {
                int m = wm * 64 + t * 16 + lr + ((sel & 1) << 3);
                int kc = s * 2 + ((sel >> 1) & 1);
                uint32_t addr = sbase + soff + (m * 4 + (kc ^ ((m >> 1) & 3))) * 16;
                ldsm_x4(afrag[t], addr + 8192);
            }
#pragma unroll
            for (int i = 0; i < 4; i++)
#pragma unroll
                for (int j = 0; j < 4; j++) {
                    const uint32_t* bp = &bfrag[j >> 1][(j & 1) * 2];
                    mma_bf16(acc[i][j], afrag[i], bp[0], bp[1]);
                }
        }
        if (it + 1 < nk) asm volatile("cp.async.wait_group 0;");
        __syncthreads();
        buf ^= 1;
    }

    int r0 = lane >> 2;
    int c0 = (lane & 3) * 2;
#pragma unroll
    for (int j = 0; j < 4; j++) {
        int gcol = bcol + wn * 32 + j * 8 + c0;
        float b0v = (gcol < 256) ? blv[gcol] : brv[gcol - 256];
        float b1v = (gcol < 256) ? blv[gcol + 1] : brv[gcol + 1 - 256];
#pragma unroll
        for (int i = 0; i < 4; i++) {
            int grow = brow + wm * 64 + i * 16 + r0;
            if (grow < Mrows) {
                float2 v = make_float2(acc[i][j][0] + b0v, acc[i][j][1] + b1v);
                *reinterpret_cast<float2*>(Cmat + (size_t)grow * 512 + gcol) = v;
            }
            if (grow + 8 < Mrows) {
                float2 v = make_float2(acc[i][j][2] + b0v, acc[i][j][3] + b1v);
                *reinterpret_cast<float2*>(Cmat + (size_t)(grow + 8) * 512 + gcol) = v;
            }
        }
    }
}

// ---------------- fused GATv2 node kernel (R9 structure, seq edge stream) ---
// Per-edge loads are now 2 sequential (srcf, ea) + the 16B/lane gather;
// perm/src/wgt indirection resolved at CSR build time.
__global__ __launch_bounds__(256) void gat_node_kernel(
    const float* __restrict__ XLR,
    const int* __restrict__ rowptr, const int* __restrict__ srcf,
    const float* __restrict__ eaArr,
    const float* __restrict__ att, const float* __restrict__ We,
    const float* __restrict__ bias, int skipSelf,
    float* __restrict__ HoutF32,
    __nv_bfloat16* __restrict__ OutHi, __nv_bfloat16* __restrict__ OutLo) {
    int wid = (blockIdx.x * blockDim.x + threadIdx.x) >> 5;
    if (wid >= NN * 2) return;
    int lane = threadIdx.x & 31;
    int node = wid >> 1;
    int h = wid & 1;
    int base = h * CH + lane * 4;
    const float4 xr = *reinterpret_cast<const float4*>(XLR + (size_t)node * 512 + 256 + base);
    const float4 av = *reinterpret_cast<const float4*>(att + base);
    const float4 wv = *reinterpret_cast<const float4*>(We + base);
    float d = 0.f;
    float4 acc = make_float4(0.f, 0.f, 0.f, 0.f);
    int i0 = rowptr[node], i1 = rowptr[node + 1];
    int idx = i0;
#define EDGE_BODY(vV, eaV, peV)                                                \
    {                                                                          \
        int s_ = vV & 0x7fffffff;                                              \
        float4 xl_ = *reinterpret_cast<const float4*>(XLR + (size_t)s_ * 512 + base); \
        float q0 = xl_.x + xr.x + eaV * wv.x;                                  \
        float q1 = xl_.y + xr.y + eaV * wv.y;                                  \
        float q2 = xl_.z + xr.z + eaV * wv.z;                                  \
        float q3 = xl_.w + xr.w + eaV * wv.w;                                  \
        q0 = q0 > 0.f ? q0 : 0.2f * q0;                                        \
        q1 = q1 > 0.f ? q1 : 0.2f * q1;                                        \
        q2 = q2 > 0.f ? q2 : 0.2f * q2;                                        \
        q3 = q3 > 0.f ? q3 : 0.2f * q3;                                        \
        peV = q0 * av.x + q1 * av.y + q2 * av.z + q3 * av.w;                   \
        xsave = xl_;                                                           \
    }
    for (; idx + 4 <= i1; idx += 4) {
        int v0 = srcf[idx], v1 = srcf[idx + 1], v2 = srcf[idx + 2], v3 = srcf[idx + 3];
        float a0 = eaArr[idx], a1 = eaArr[idx + 1], a2 = eaArr[idx + 2], a3 = eaArr[idx + 3];
        float p0, p1, p2, p3;
        float4 xsave;
        float4 x0, x1, x2, x3;
        EDGE_BODY(v0, a0, p0); x0 = xsave;
        EDGE_BODY(v1, a1, p1); x1 = xsave;
        EDGE_BODY(v2, a2, p2); x2 = xsave;
        EDGE_BODY(v3, a3, p3); x3 = xsave;
#pragma unroll
        for (int off = 16; off >= 1; off >>= 1) {
            p0 += __shfl_xor_sync(0xffffffffu, p0, off);
            p1 += __shfl_xor_sync(0xffffffffu, p1, off);
            p2 += __shfl_xor_sync(0xffffffffu, p2, off);
            p3 += __shfl_xor_sync(0xffffffffu, p3, off);
        }
        float m0 = (skipSelf && v0 < 0) ? 0.f : 1.f;
        float m1 = (skipSelf && v1 < 0) ? 0.f : 1.f;
        float m2 = (skipSelf && v2 < 0) ? 0.f : 1.f;
        float m3 = (skipSelf && v3 < 0) ? 0.f : 1.f;
        float pe0 = __expf(p0) * m0, pe1 = __expf(p1) * m1;
        float pe2 = __expf(p2) * m2, pe3 = __expf(p3) * m3;
        d += (pe0 + pe1) + (pe2 + pe3);
        acc.x += pe0 * x0.x + pe1 * x1.x + pe2 * x2.x + pe3 * x3.x;
        acc.y += pe0 * x0.y + pe1 * x1.y + pe2 * x2.y + pe3 * x3.y;
        acc.z += pe0 * x0.z + pe1 * x1.z + pe2 * x2.z + pe3 * x3.z;
        acc.w += pe0 * x0.w + pe1 * x1.w + pe2 * x2.w + pe3 * x3.w;
    }
    for (; idx < i1; idx++) {
        int v = srcf[idx];
        float a = eaArr[idx];
        float p;
        float4 xsave;
        EDGE_BODY(v, a, p);
#pragma unroll
        for (int off = 16; off >= 1; off >>= 1) p += __shfl_xor_sync(0xffffffffu, p, off);
        float m = (skipSelf && v < 0) ? 0.f : 1.f;
        float pe = __expf(p) * m;
        d += pe;
        acc.x += pe * xsave.x;
        acc.y += pe * xsave.y;
        acc.z += pe * xsave.z;
        acc.w += pe * xsave.w;
    }
#undef EDGE_BODY
    float inv = (d > 0.f) ? 1.f / (d + 1e-16f) : 0.f;
    const float4 bv = *reinterpret_cast<const float4*>(bias + base);
    float o0 = acc.x * inv + bv.x;
    float o1 = acc.y * inv + bv.y;
    float o2 = acc.z * inv + bv.z;
    float o3 = acc.w * inv + bv.w;
    o0 = o0 > 0.f ? o0 : expm1f(o0);
    o1 = o1 > 0.f ? o1 : expm1f(o1);
    o2 = o2 > 0.f ? o2 : expm1f(o2);
    o3 = o3 > 0.f ? o3 : expm1f(o3);
    if (HoutF32) {
        *reinterpret_cast<float4*>(HoutF32 + (size_t)node * HC + base) =
            make_float4(o0, o1, o2, o3);
    } else {
        __nv_bfloat16 h0, h1, h2, h3, l0, l1, l2, l3;
        split_bf16(o0, h0, l0); split_bf16(o1, h1, l1);
        split_bf16(o2, h2, l2); split_bf16(o3, h3, l3);
        size_t ofs = (size_t)node * HC + base;
        *reinterpret_cast<uint2*>(OutHi + ofs) = make_uint2(pack_bf16(h0, h1), pack_bf16(h2, h3));
        *reinterpret_cast<uint2*>(OutLo + ofs) = make_uint2(pack_bf16(l0, l1), pack_bf16(l2, l3));
    }
}

// ---------------- final classifier (exact R9) -------------------------------
__global__ __launch_bounds__(256) void fc_kernel(const float* __restrict__ Hin,
                                                 const float* __restrict__ W,
                                                 const float* __restrict__ b,
                                                 float* __restrict__ out) {
    int wid = (blockIdx.x * blockDim.x + threadIdx.x) >> 5;
    if (wid >= NN) return;
    int lane = threadIdx.x & 31;
    float acc[NCLASS];
#pragma unroll
    for (int k = 0; k < NCLASS; k++) acc[k] = 0.f;
#pragma unroll
    for (int j0 = 0; j0 < HC; j0 += 32) {
        float hv = Hin[(size_t)wid * HC + j0 + lane];
        const float* wr = W + (size_t)(j0 + lane) * NCLASS;
#pragma unroll
        for (int k = 0; k < NCLASS; k++) acc[k] += hv * __ldg(wr + k);
    }
#pragma unroll
    for (int k = 0; k < NCLASS; k++) {
#pragma unroll
        for (int off = 16; off >= 1; off >>= 1)
            acc[k] += __shfl_xor_sync(0xffffffffu, acc[k], off);
    }
    if (lane == 0) {
#pragma unroll
        for (int k = 0; k < NCLASS; k++) out[(size_t)wid * NCLASS + k] = acc[k] + b[k];
    }
}

// ---------------- launch -----------------------------------------------------
extern "C" void kernel_launch(void* const* d_in, const int* in_sizes, int n_in,
                              void* d_out, int out_size) {
    const float* x = (const float*)d_in[0];
    const void* ei = d_in[1];
    const float* wgt = (const float*)d_in[2];
    const float *Wl[3], *bl[3], *Wr[3], *br[3], *We[3], *att[3], *bb[3];
    for (int i = 0; i < 3; i++) {
        int bse = 3 + 7 * i;
        Wl[i] = (const float*)d_in[bse + 0];
        bl[i] = (const float*)d_in[bse + 1];
        Wr[i] = (const float*)d_in[bse + 2];
        br[i] = (const float*)d_in[bse + 3];
        We[i] = (const float*)d_in[bse + 4];
        att[i] = (const float*)d_in[bse + 5];
        bb[i] = (const float*)d_in[bse + 6];
    }
    const float* fcW = (const float*)d_in[24];
    const float* fcb = (const float*)d_in[25];
    float* out = (float*)d_out;

    int *psrc, *pdst, *pcnt, *pcursor, *prow1, *psrcf;
    float *pea, *pXLR, *pHA;
    __nv_bfloat16 *pAhi, *pAlo, *pWhi, *pWlo;
    cudaGetSymbolAddress((void**)&psrc, g_src);
    cudaGetSymbolAddress((void**)&pdst, g_dst);
    cudaGetSymbolAddress((void**)&pcnt, g_cnt);
    cudaGetSymbolAddress((void**)&pcursor, g_cursor);
    cudaGetSymbolAddress((void**)&prow1, g_rowptr1);
    cudaGetSymbolAddress((void**)&psrcf, g_srcf);
    cudaGetSymbolAddress((void**)&pea, g_ea);
    cudaGetSymbolAddress((void**)&pXLR, g_XLR);
    cudaGetSymbolAddress((void**)&pHA, g_HA);
    cudaGetSymbolAddress((void**)&pAhi, g_Ahi);
    cudaGetSymbolAddress((void**)&pAlo, g_Alo);
    cudaGetSymbolAddress((void**)&pWhi, g_Whi);
    cudaGetSymbolAddress((void**)&pWlo, g_Wlo);

    cudaFuncSetAttribute(gemm_bf16_ldsm_kernel,
                         cudaFuncAttributeMaxDynamicSharedMemorySize, 65536);

    // prep: zero counts, fused decode+selfloops+hist; weight mean (before scatter)
    zero_int_kernel<<<(NN + 255) / 256, 256>>>(pcnt, NN);
    convert_edges_hist_kernel<<<(ESLN + 255) / 256, 256>>>((const unsigned int*)ei,
                                                           psrc, pdst, pcnt);
    mean_partial_kernel<<<256, 256>>>(wgt);
    mean_final_kernel<<<1, 256>>>();

    // CSR (with self loops); scatter resolves src/wgt indirection
    scan_local_kernel<<<NB0, 1024>>>(pcnt, prow1);
    scan_bsum_kernel<<<1, 64>>>(prow1);
    scan_add_kernel<<<NB0, 1024>>>(prow1, pcursor);
    scatter_kernel<<<(ESLN + 255) / 256, 256>>>(psrc, pdst, wgt, pcursor,
                                                psrcf, pea, ESLN);

    // weights -> bf16 hi/lo; x -> bf16 hi/lo
    w_convert_kernel<<<(640 * 512 + 255) / 256, 256>>>(Wl[0], Wr[0], Wl[1], Wr[1], Wl[2], Wr[2]);
    a_convert_kernel<<<(NN * FIN / 4 + 255) / 256, 256>>>(x, pAhi, pAlo, NN * FIN);

    dim3 ggrid(4, (NN + 127) / 128);
    int node_blocks = (NN * 2 * 32 + 255) / 256;  // one warp per (node, head)

    // Layer 0 (mask self loops)
    gemm_bf16_ldsm_kernel<<<ggrid, 256, 65536>>>(pAhi, pAlo, NN, FIN,
                                                 pWhi, pWlo, bl[0], br[0], pXLR);
    gat_node_kernel<<<node_blocks, 256>>>(pXLR, prow1, psrcf, pea,
                                          att[0], We[0], bb[0], 1,
                                          nullptr, pAhi, pAlo);
    // Layer 1
    gemm_bf16_ldsm_kernel<<<ggrid, 256, 65536>>>(pAhi, pAlo, NN, HC,
                                                 pWhi + 128 * 512, pWlo + 128 * 512,
                                                 bl[1], br[1], pXLR);
    gat_node_kernel<<<node_blocks, 256>>>(pXLR, prow1, psrcf, pea,
                                          att[1], We[1], bb[1], 0,
                                          nullptr, pAhi, pAlo);
    // Layer 2
    gemm_bf16_ldsm_kernel<<<ggrid, 256, 65536>>>(pAhi, pAlo, NN, HC,
                                                 pWhi + 384 * 512, pWlo + 384 * 512,
                                                 bl[2], br[2], pXLR);
    gat_node_kernel<<<node_blocks, 256>>>(pXLR, prow1, psrcf, pea,
                                          att[2], We[2], bb[2], 0,
                                          pHA, nullptr, nullptr);
    // Classifier
    fc_kernel<<<(NN * 32 + 255) / 256, 256>>>(pHA, fcW, fcb, out);
}

// round 17
// speedup vs baseline: 1.1876x; 1.0038x over previous
#include <cuda_runtime.h>
#include <cuda_bf16.h>
#include <math.h>
#include <stdint.h>

#define NN 50000
#define EE 500000
#define ESLN 550000   // EE + NN (edges with self loops)
#define FIN 128
#define HC 256
#define CH 128
#define NCLASS 10
#define NB0 49        // ceil(NN/1024)

// ---------------- scratch (static __device__ globals; no allocation) -------
__device__ int   g_src[ESLN];
__device__ int   g_dst[ESLN];
__device__ int   g_cnt[NN];
__device__ int   g_cursor[NN];
__device__ int   g_rowptr1[NN + 1];
__device__ int   g_srcf[ESLN];   // per-CSR-slot: src | (selfloop << 31)
__device__ float g_ea[ESLN];     // per-CSR-slot: edge attr (wgt or wmean)
__device__ float g_XLR[(size_t)NN * 512];   // [N,512]: 0..255 = xl, 256..511 = xr
__device__ float g_HA[(size_t)NN * HC];     // final layer f32 output
__device__ __nv_bfloat16 g_Ahi[(size_t)NN * HC];
__device__ __nv_bfloat16 g_Alo[(size_t)NN * HC];
__device__ __nv_bfloat16 g_Whi[640 * 512];  // layer0 rows 0-127, l1 128-383, l2 384-639
__device__ __nv_bfloat16 g_Wlo[640 * 512];
__device__ float g_partial[256];
__device__ float g_wmean;
__device__ int   g_bsum[64];

// ---------------- small utility kernels ------------------------------------
__global__ void zero_int_kernel(int* p, int n) {
    int i = blockIdx.x * blockDim.x + threadIdx.x;
    if (i < n) p[i] = 0;
}

// edge decode (int32/int64 robust) + self loops + dst histogram (fused).
__global__ void convert_edges_hist_kernel(const unsigned int* __restrict__ ei,
                                          int* __restrict__ src, int* __restrict__ dst,
                                          int* __restrict__ cnt) {
    __shared__ int s_is64;
    if (threadIdx.x == 0) {
        unsigned int acc = 0;
#pragma unroll
        for (int k = 0; k < 32; k++) acc |= ei[2 * k + 1];
        s_is64 = (acc == 0u) ? 1 : 0;
    }
    __syncthreads();
    int is64 = s_is64;
    int i = blockIdx.x * blockDim.x + threadIdx.x;
    if (i >= ESLN) return;
    int s, d;
    if (i < EE) {
        if (is64) {
            const long long* p = reinterpret_cast<const long long*>(ei);
            s = (int)p[i];
            d = (int)p[EE + i];
        } else {
            const int* p = reinterpret_cast<const int*>(ei);
            s = p[i];
            d = p[EE + i];
        }
    } else {
        s = d = i - EE;
    }
    src[i] = s;
    dst[i] = d;
    atomicAdd(&cnt[d], 1);
}

__global__ void mean_partial_kernel(const float* __restrict__ w) {
    __shared__ float s[256];
    float acc = 0.f;
    for (int i = blockIdx.x * 256 + threadIdx.x; i < EE; i += 256 * 256) acc += w[i];
    s[threadIdx.x] = acc;
    __syncthreads();
    for (int off = 128; off > 0; off >>= 1) {
        if (threadIdx.x < off) s[threadIdx.x] += s[threadIdx.x + off];
        __syncthreads();
    }
    if (threadIdx.x == 0) g_partial[blockIdx.x] = s[0];
}

__global__ void mean_final_kernel() {
    __shared__ float s[256];
    s[threadIdx.x] = g_partial[threadIdx.x];
    __syncthreads();
    for (int off = 128; off > 0; off >>= 1) {
        if (threadIdx.x < off) s[threadIdx.x] += s[threadIdx.x + off];
        __syncthreads();
    }
    if (threadIdx.x == 0) g_wmean = s[0] / (float)EE;
}

// ---- 3-phase scan ----
__global__ void scan_local_kernel(const int* __restrict__ cnt, int* __restrict__ rowptr) {
    __shared__ int s[1024];
    int t = threadIdx.x;
    int i = blockIdx.x * 1024 + t;
    int v = (i < NN) ? cnt[i] : 0;
    s[t] = v;
    __syncthreads();
    for (int off = 1; off < 1024; off <<= 1) {
        int x = s[t];
        int y = (t >= off) ? s[t - off] : 0;
        __syncthreads();
        s[t] = x + y;
        __syncthreads();
    }
    if (i < NN) rowptr[i] = s[t] - v;
    if (t == 1023) g_bsum[blockIdx.x] = s[1023];
}

__global__ void scan_bsum_kernel(int* __restrict__ rowptr) {
    __shared__ int s[64];
    int t = threadIdx.x;
    int v = (t < NB0) ? g_bsum[t] : 0;
    s[t] = v;
    __syncthreads();
    for (int off = 1; off < 64; off <<= 1) {
        int x = s[t];
        int y = (t >= off) ? s[t - off] : 0;
        __syncthreads();
        s[t] = x + y;
        __syncthreads();
    }
    if (t < NB0) g_bsum[t] = s[t] - v;
    if (t == 63) rowptr[NN] = s[63];
}

__global__ void scan_add_kernel(int* __restrict__ rowptr, int* __restrict__ cursor) {
    int i = blockIdx.x * 1024 + threadIdx.x;
    if (i < NN) {
        int r = rowptr[i] + g_bsum[blockIdx.x];
        rowptr[i] = r;
        cursor[i] = r;
    }
}

// Scatter resolves the indirection at build time: stores src|flag and edge
// attr at the permuted slot, so the node kernels read sequentially.
__global__ void scatter_kernel(const int* __restrict__ src, const int* __restrict__ dst,
                               const float* __restrict__ wgt, int* __restrict__ cursor,
                               int* __restrict__ srcf, float* __restrict__ ea, int count) {
    int e = blockIdx.x * blockDim.x + threadIdx.x;
    if (e < count) {
        int p = atomicAdd(&cursor[dst[e]], 1);
        int flag = (e >= EE) ? (int)0x80000000 : 0;
        srcf[p] = src[e] | flag;
        ea[p] = (e < EE) ? wgt[e] : g_wmean;
    }
}

// ---------------- bf16 helpers ----------------------------------------------
__device__ __forceinline__ uint32_t pack_bf16(__nv_bfloat16 a, __nv_bfloat16 b) {
    __nv_bfloat162 t = __halves2bfloat162(a, b);
    return *reinterpret_cast<uint32_t*>(&t);
}

__device__ __forceinline__ void split_bf16(float x, __nv_bfloat16& h, __nv_bfloat16& l) {
    h = __float2bfloat16_rn(x);
    l = __float2bfloat16_rn(x - __bfloat162float(h));
}

__device__ __forceinline__ void mma_bf16(float* c, const uint32_t* a, uint32_t b0, uint32_t b1) {
    asm volatile(
        "mma.sync.aligned.m16n8k16.row.col.f32.bf16.bf16.f32 "
        "{%0,%1,%2,%3}, {%4,%5,%6,%7}, {%8,%9}, {%0,%1,%2,%3};"
        : "+f"(c[0]), "+f"(c[1]), "+f"(c[2]), "+f"(c[3])
        : "r"(a[0]), "r"(a[1]), "r"(a[2]), "r"(a[3]), "r"(b0), "r"(b1));
}

__device__ __forceinline__ void ldsm_x4(uint32_t* r, uint32_t saddr) {
    asm volatile("ldmatrix.sync.aligned.m8n8.x4.shared.b16 {%0,%1,%2,%3}, [%4];"
                 : "=r"(r[0]), "=r"(r[1]), "=r"(r[2]), "=r"(r[3]) : "r"(saddr));
}

__device__ __forceinline__ void ldsm_x4_t(uint32_t* r, uint32_t saddr) {
    asm volatile("ldmatrix.sync.aligned.m8n8.x4.trans.shared.b16 {%0,%1,%2,%3}, [%4];"
                 : "=r"(r[0]), "=r"(r[1]), "=r"(r[2]), "=r"(r[3]) : "r"(saddr));
}

__device__ __forceinline__ void cp_async16(uint32_t saddr, const void* g, int sz) {
    asm volatile("cp.async.cg.shared.global [%0], [%1], 16, %2;"
                 :: "r"(saddr), "l"(g), "r"(sz));
}

// ---------------- conversion kernels ----------------------------------------
__global__ void a_convert_kernel(const float* __restrict__ A,
                                 __nv_bfloat16* __restrict__ hi,
                                 __nv_bfloat16* __restrict__ lo, int total) {
    int i = (blockIdx.x * blockDim.x + threadIdx.x) * 4;
    if (i >= total) return;
    float4 v = *reinterpret_cast<const float4*>(A + i);
    __nv_bfloat16 h0, h1, h2, h3, l0, l1, l2, l3;
    split_bf16(v.x, h0, l0); split_bf16(v.y, h1, l1);
    split_bf16(v.z, h2, l2); split_bf16(v.w, h3, l3);
    *reinterpret_cast<uint2*>(hi + i) = make_uint2(pack_bf16(h0, h1), pack_bf16(h2, h3));
    *reinterpret_cast<uint2*>(lo + i) = make_uint2(pack_bf16(l0, l1), pack_bf16(l2, l3));
}

__global__ void w_convert_kernel(const float* __restrict__ Wl0, const float* __restrict__ Wr0,
                                 const float* __restrict__ Wl1, const float* __restrict__ Wr1,
                                 const float* __restrict__ Wl2, const float* __restrict__ Wr2) {
    int i = blockIdx.x * blockDim.x + threadIdx.x;
    if (i >= 640 * 512) return;
    int row = i >> 9, col = i & 511;
    const float *Wl, *Wr;
    int k;
    if (row < 128) { Wl = Wl0; Wr = Wr0; k = row; }
    else if (row < 384) { Wl = Wl1; Wr = Wr1; k = row - 128; }
    else { Wl = Wl2; Wr = Wr2; k = row - 384; }
    float v = (col < 256) ? Wl[k * 256 + col] : Wr[k * 256 + col - 256];
    __nv_bfloat16 h, l;
    split_bf16(v, h, l);
    g_Whi[i] = h;
    g_Wlo[i] = l;
}

// ---------------- GEMM: C[N,512] = A[N,K] @ W + bias (exact R14) ------------
__global__ __launch_bounds__(256, 2) void gemm_bf16_ldsm_kernel(
    const __nv_bfloat16* __restrict__ Ahi, const __nv_bfloat16* __restrict__ Alo,
    int Mrows, int K,
    const __nv_bfloat16* __restrict__ Whi, const __nv_bfloat16* __restrict__ Wlo,
    const float* __restrict__ blv, const float* __restrict__ brv,
    float* __restrict__ Cmat) {
    extern __shared__ uint8_t smem[];
    uint32_t sbase = (uint32_t)__cvta_generic_to_shared(smem);
    const int bcol = blockIdx.x * 128;
    const int brow = blockIdx.y * 128;
    const int tid = threadIdx.x;
    const int lane = tid & 31;
    const int warp = tid >> 5;
    const int wm = warp >> 2;
    const int wn = warp & 3;

    float acc[4][4][4];
#pragma unroll
    for (int i = 0; i < 4; i++)
#pragma unroll
        for (int j = 0; j < 4; j++)
#pragma unroll
            for (int r = 0; r < 4; r++) acc[i][j][r] = 0.f;

    auto prefetch = [&](int kt, int soff) {
#pragma unroll
        for (int i = 0; i < 2; i++) {
            int c = tid + i * 256;
            int m = c >> 2, kc = c & 3;
            int grow = brow + m;
            int sz = (grow < Mrows) ? 16 : 0;
            uint32_t da = sbase + soff + (m * 4 + (kc ^ ((m >> 1) & 3))) * 16;
            size_t gofs = (size_t)grow * K + kt + kc * 8;
            cp_async16(da, Ahi + gofs, sz);
            cp_async16(da + 8192, Alo + gofs, sz);
        }
#pragma unroll
        for (int i = 0; i < 2; i++) {
            int c = tid + i * 256;
            int k = c >> 4, nc = c & 15;
            uint32_t db = sbase + soff + 16384 + (k * 16 + (nc ^ (k & 7))) * 16;
            size_t gofs = (size_t)(kt + k) * 512 + bcol + nc * 8;
            cp_async16(db, Whi + gofs, 16);
            cp_async16(db + 8192, Wlo + gofs, 16);
        }
        asm volatile("cp.async.commit_group;");
    };

    const int nk = K >> 5;
    prefetch(0, 0);
    asm volatile("cp.async.wait_group 0;");
    __syncthreads();

    const int lr = lane & 7;
    const int sel = lane >> 3;
    int buf = 0;
    for (int it = 0; it < nk; it++) {
        if (it + 1 < nk) prefetch((it + 1) << 5, (buf ^ 1) * 32768);
        int soff = buf * 32768;
#pragma unroll
        for (int s = 0; s < 2; s++) {
            uint32_t afrag[4][4], bfrag[2][4], b2frag[2][4];
#pragma unroll
            for (int t = 0; t < 4; t++) {
                int m = wm * 64 + t * 16 + lr + ((sel & 1) << 3);
                int kc = s * 2 + ((sel >> 1) & 1);
                uint32_t addr = sbase + soff + (m * 4 + (kc ^ ((m >> 1) & 3))) * 16;
                ldsm_x4(afrag[t], addr);
            }
#pragma unroll
            for (int j2 = 0; j2 < 2; j2++) {
                int k = s * 16 + ((sel & 1) << 3) + lr;
                int nt = wn * 4 + 2 * j2 + ((sel >> 1) & 1);
                uint32_t addr = sbase + soff + 16384 + (k * 16 + (nt ^ (k & 7))) * 16;
                ldsm_x4_t(bfrag[j2], addr);
            }
#pragma unroll
            for (int i = 0; i < 4; i++)
#pragma unroll
                for (int j = 0; j < 4; j++) {
                    const uint32_t* bp = &bfrag[j >> 1][(j & 1) * 2];
                    mma_bf16(acc[i][j], afrag[i], bp[0], bp[1]);
                }
#pragma unroll
            for (int j2 = 0; j2 < 2; j2++) {
                int k = s * 16 + ((sel & 1) << 3) + lr;
                int nt = wn * 4 + 2 * j2 + ((sel >> 1) & 1);
                uint32_t addr = sbase + soff + 16384 + (k * 16 + (nt ^ (k & 7))) * 16;
                ldsm_x4_t(b2frag[j2], addr + 8192);
            }
#pragma unroll
            for (int i = 0; i < 4; i++)
#pragma unroll
                for (int j = 0; j < 4; j++) {
                    const uint32_t* bp = &b2frag[j >> 1][(j & 1) * 2];
                    mma_bf16(acc[i][j], afrag[i], bp[0], bp[1]);
                }
#pragma unroll
            for (int t = 0; t < 4; t++) {
                int m = wm * 64 + t * 16 + lr + ((sel & 1) << 3);
                int kc = s * 2 + ((sel >> 1) & 1);
                uint32_t addr = sbase + soff + (m * 4 + (kc ^ ((m >> 1) & 3))) * 16;
                ldsm_x4(afrag[t], addr + 8192);
            }
#pragma unroll
            for (int i = 0; i < 4; i++)
#pragma unroll
                for (int j = 0; j < 4; j++) {
                    const uint32_t* bp = &bfrag[j >> 1][(j & 1) * 2];
                    mma_bf16(acc[i][j], afrag[i], bp[0], bp[1]);
                }
        }
        if (it + 1 < nk) asm volatile("cp.async.wait_group 0;");
        __syncthreads();
        buf ^= 1;
    }

    int r0 = lane >> 2;
    int c0 = (lane & 3) * 2;
#pragma unroll
    for (int j = 0; j < 4; j++) {
        int gcol = bcol + wn * 32 + j * 8 + c0;
        float b0v = (gcol < 256) ? blv[gcol] : brv[gcol - 256];
        float b1v = (gcol < 256) ? blv[gcol + 1] : brv[gcol + 1 - 256];
#pragma unroll
        for (int i = 0; i < 4; i++) {
            int grow = brow + wm * 64 + i * 16 + r0;
            if (grow < Mrows) {
                float2 v = make_float2(acc[i][j][0] + b0v, acc[i][j][1] + b1v);
                *reinterpret_cast<float2*>(Cmat + (size_t)grow * 512 + gcol) = v;
            }
            if (grow + 8 < Mrows) {
                float2 v = make_float2(acc[i][j][2] + b0v, acc[i][j][3] + b1v);
                *reinterpret_cast<float2*>(Cmat + (size_t)(grow + 8) * 512 + gcol) = v;
            }
        }
    }
}

// ---------------- fused GATv2 node kernel (R14, seq edge stream) ------------
__global__ __launch_bounds__(256) void gat_node_kernel(
    const float* __restrict__ XLR,
    const int* __restrict__ rowptr, const int* __restrict__ srcf,
    const float* __restrict__ eaArr,
    const float* __restrict__ att, const float* __restrict__ We,
    const float* __restrict__ bias, int skipSelf,
    float* __restrict__ HoutF32,
    __nv_bfloat16* __restrict__ OutHi, __nv_bfloat16* __restrict__ OutLo) {
    int wid = (blockIdx.x * blockDim.x + threadIdx.x) >> 5;
    if (wid >= NN * 2) return;
    int lane = threadIdx.x & 31;
    int node = wid >> 1;
    int h = wid & 1;
    int base = h * CH + lane * 4;
    const float4 xr = *reinterpret_cast<const float4*>(XLR + (size_t)node * 512 + 256 + base);
    const float4 av = *reinterpret_cast<const float4*>(att + base);
    const float4 wv = *reinterpret_cast<const float4*>(We + base);
    float d = 0.f;
    float4 acc = make_float4(0.f, 0.f, 0.f, 0.f);
    int i0 = rowptr[node], i1 = rowptr[node + 1];
    int idx = i0;
#define EDGE_BODY(vV, eaV, peV)                                                \
    {                                                                          \
        int s_ = vV & 0x7fffffff;                                              \
        float4 xl_ = *reinterpret_cast<const float4*>(XLR + (size_t)s_ * 512 + base); \
        float q0 = xl_.x + xr.x + eaV * wv.x;                                  \
        float q1 = xl_.y + xr.y + eaV * wv.y;                                  \
        float q2 = xl_.z + xr.z + eaV * wv.z;                                  \
        float q3 = xl_.w + xr.w + eaV * wv.w;                                  \
        q0 = q0 > 0.f ? q0 : 0.2f * q0;                                        \
        q1 = q1 > 0.f ? q1 : 0.2f * q1;                                        \
        q2 = q2 > 0.f ? q2 : 0.2f * q2;                                        \
        q3 = q3 > 0.f ? q3 : 0.2f * q3;                                        \
        peV = q0 * av.x + q1 * av.y + q2 * av.z + q3 * av.w;                   \
        xsave = xl_;                                                           \
    }
    for (; idx + 4 <= i1; idx += 4) {
        int v0 = srcf[idx], v1 = srcf[idx + 1], v2 = srcf[idx + 2], v3 = srcf[idx + 3];
        float a0 = eaArr[idx], a1 = eaArr[idx + 1], a2 = eaArr[idx + 2], a3 = eaArr[idx + 3];
        float p0, p1, p2, p3;
        float4 xsave;
        float4 x0, x1, x2, x3;
        EDGE_BODY(v0, a0, p0); x0 = xsave;
        EDGE_BODY(v1, a1, p1); x1 = xsave;
        EDGE_BODY(v2, a2, p2); x2 = xsave;
        EDGE_BODY(v3, a3, p3); x3 = xsave;
#pragma unroll
        for (int off = 16; off >= 1; off >>= 1) {
            p0 += __shfl_xor_sync(0xffffffffu, p0, off);
            p1 += __shfl_xor_sync(0xffffffffu, p1, off);
            p2 += __shfl_xor_sync(0xffffffffu, p2, off);
            p3 += __shfl_xor_sync(0xffffffffu, p3, off);
        }
        float m0 = (skipSelf && v0 < 0) ? 0.f : 1.f;
        float m1 = (skipSelf && v1 < 0) ? 0.f : 1.f;
        float m2 = (skipSelf && v2 < 0) ? 0.f : 1.f;
        float m3 = (skipSelf && v3 < 0) ? 0.f : 1.f;
        float pe0 = __expf(p0) * m0, pe1 = __expf(p1) * m1;
        float pe2 = __expf(p2) * m2, pe3 = __expf(p3) * m3;
        d += (pe0 + pe1) + (pe2 + pe3);
        acc.x += pe0 * x0.x + pe1 * x1.x + pe2 * x2.x + pe3 * x3.x;
        acc.y += pe0 * x0.y + pe1 * x1.y + pe2 * x2.y + pe3 * x3.y;
        acc.z += pe0 * x0.z + pe1 * x1.z + pe2 * x2.z + pe3 * x3.z;
        acc.w += pe0 * x0.w + pe1 * x1.w + pe2 * x2.w + pe3 * x3.w;
    }
    for (; idx < i1; idx++) {
        int v = srcf[idx];
        float a = eaArr[idx];
        float p;
        float4 xsave;
        EDGE_BODY(v, a, p);
#pragma unroll
        for (int off = 16; off >= 1; off >>= 1) p += __shfl_xor_sync(0xffffffffu, p, off);
        float m = (skipSelf && v < 0) ? 0.f : 1.f;
        float pe = __expf(p) * m;
        d += pe;
        acc.x += pe * xsave.x;
        acc.y += pe * xsave.y;
        acc.z += pe * xsave.z;
        acc.w += pe * xsave.w;
    }
#undef EDGE_BODY
    float inv = (d > 0.f) ? 1.f / (d + 1e-16f) : 0.f;
    const float4 bv = *reinterpret_cast<const float4*>(bias + base);
    float o0 = acc.x * inv + bv.x;
    float o1 = acc.y * inv + bv.y;
    float o2 = acc.z * inv + bv.z;
    float o3 = acc.w * inv + bv.w;
    o0 = o0 > 0.f ? o0 : expm1f(o0);
    o1 = o1 > 0.f ? o1 : expm1f(o1);
    o2 = o2 > 0.f ? o2 : expm1f(o2);
    o3 = o3 > 0.f ? o3 : expm1f(o3);
    if (HoutF32) {
        *reinterpret_cast<float4*>(HoutF32 + (size_t)node * HC + base) =
            make_float4(o0, o1, o2, o3);
    } else {
        __nv_bfloat16 h0, h1, h2, h3, l0, l1, l2, l3;
        split_bf16(o0, h0, l0); split_bf16(o1, h1, l1);
        split_bf16(o2, h2, l2); split_bf16(o3, h3, l3);
        size_t ofs = (size_t)node * HC + base;
        *reinterpret_cast<uint2*>(OutHi + ofs) = make_uint2(pack_bf16(h0, h1), pack_bf16(h2, h3));
        *reinterpret_cast<uint2*>(OutLo + ofs) = make_uint2(pack_bf16(l0, l1), pack_bf16(l2, l3));
    }
}

// ---------------- final classifier (exact R14) ------------------------------
__global__ __launch_bounds__(256) void fc_kernel(const float* __restrict__ Hin,
                                                 const float* __restrict__ W,
                                                 const float* __restrict__ b,
                                                 float* __restrict__ out) {
    int wid = (blockIdx.x * blockDim.x + threadIdx.x) >> 5;
    if (wid >= NN) return;
    int lane = threadIdx.x & 31;
    float acc[NCLASS];
#pragma unroll
    for (int k = 0; k < NCLASS; k++) acc[k] = 0.f;
#pragma unroll
    for (int j0 = 0; j0 < HC; j0 += 32) {
        float hv = Hin[(size_t)wid * HC + j0 + lane];
        const float* wr = W + (size_t)(j0 + lane) * NCLASS;
#pragma unroll
        for (int k = 0; k < NCLASS; k++) acc[k] += hv * __ldg(wr + k);
    }
#pragma unroll
    for (int k = 0; k < NCLASS; k++) {
#pragma unroll
        for (int off = 16; off >= 1; off >>= 1)
            acc[k] += __shfl_xor_sync(0xffffffffu, acc[k], off);
    }
    if (lane == 0) {
#pragma unroll
        for (int k = 0; k < NCLASS; k++) out[(size_t)wid * NCLASS + k] = acc[k] + b[k];
    }
}

// ---------------- launch -----------------------------------------------------
extern "C" void kernel_launch(void* const* d_in, const int* in_sizes, int n_in,
                              void* d_out, int out_size) {
    const float* x = (const float*)d_in[0];
    const void* ei = d_in[1];
    const float* wgt = (const float*)d_in[2];
    const float *Wl[3], *bl[3], *Wr[3], *br[3], *We[3], *att[3], *bb[3];
    for (int i = 0; i < 3; i++) {
        int bse = 3 + 7 * i;
        Wl[i] = (const float*)d_in[bse + 0];
        bl[i] = (const float*)d_in[bse + 1];
        Wr[i] = (const float*)d_in[bse + 2];
        br[i] = (const float*)d_in[bse + 3];
        We[i] = (const float*)d_in[bse + 4];
        att[i] = (const float*)d_in[bse + 5];
        bb[i] = (const float*)d_in[bse + 6];
    }
    const float* fcW = (const float*)d_in[24];
    const float* fcb = (const float*)d_in[25];
    float* out = (float*)d_out;

    int *psrc, *pdst, *pcnt, *pcursor, *prow1, *psrcf;
    float *pea, *pXLR, *pHA;
    __nv_bfloat16 *pAhi, *pAlo, *pWhi, *pWlo;
    cudaGetSymbolAddress((void**)&psrc, g_src);
    cudaGetSymbolAddress((void**)&pdst, g_dst);
    cudaGetSymbolAddress((void**)&pcnt, g_cnt);
    cudaGetSymbolAddress((void**)&pcursor, g_cursor);
    cudaGetSymbolAddress((void**)&prow1, g_rowptr1);
    cudaGetSymbolAddress((void**)&psrcf, g_srcf);
    cudaGetSymbolAddress((void**)&pea, g_ea);
    cudaGetSymbolAddress((void**)&pXLR, g_XLR);
    cudaGetSymbolAddress((void**)&pHA, g_HA);
    cudaGetSymbolAddress((void**)&pAhi, g_Ahi);
    cudaGetSymbolAddress((void**)&pAlo, g_Alo);
    cudaGetSymbolAddress((void**)&pWhi, g_Whi);
    cudaGetSymbolAddress((void**)&pWlo, g_Wlo);

    cudaFuncSetAttribute(gemm_bf16_ldsm_kernel,
                         cudaFuncAttributeMaxDynamicSharedMemorySize, 65536);

    // prep: zero counts, fused decode+selfloops+hist; weight mean (before scatter)
    zero_int_kernel<<<(NN + 255) / 256, 256>>>(pcnt, NN);
    convert_edges_hist_kernel<<<(ESLN + 255) / 256, 256>>>((const unsigned int*)ei,
                                                           psrc, pdst, pcnt);
    mean_partial_kernel<<<256, 256>>>(wgt);
    mean_final_kernel<<<1, 256>>>();

    // CSR (with self loops); scatter resolves src/wgt indirection
    scan_local_kernel<<<NB0, 1024>>>(pcnt, prow1);
    scan_bsum_kernel<<<1, 64>>>(prow1);
    scan_add_kernel<<<NB0, 1024>>>(prow1, pcursor);
    scatter_kernel<<<(ESLN + 255) / 256, 256>>>(psrc, pdst, wgt, pcursor,
                                                psrcf, pea, ESLN);

    // weights -> bf16 hi/lo; x -> bf16 hi/lo
    w_convert_kernel<<<(640 * 512 + 255) / 256, 256>>>(Wl[0], Wr[0], Wl[1], Wr[1], Wl[2], Wr[2]);
    a_convert_kernel<<<(NN * FIN / 4 + 255) / 256, 256>>>(x, pAhi, pAlo, NN * FIN);

    dim3 ggrid(4, (NN + 127) / 128);
    int node_blocks = (NN * 2 * 32 + 255) / 256;  // one warp per (node, head)

    // Layer 0 (mask self loops)
    gemm_bf16_ldsm_kernel<<<ggrid, 256, 65536>>>(pAhi, pAlo, NN, FIN,
                                                 pWhi, pWlo, bl[0], br[0], pXLR);
    gat_node_kernel<<<node_blocks, 256>>>(pXLR, prow1, psrcf, pea,
                                          att[0], We[0], bb[0], 1,
                                          nullptr, pAhi, pAlo);
    // Layer 1
    gemm_bf16_ldsm_kernel<<<ggrid, 256, 65536>>>(pAhi, pAlo, NN, HC,
                                                 pWhi + 128 * 512, pWlo + 128 * 512,
                                                 bl[1], br[1], pXLR);
    gat_node_kernel<<<node_blocks, 256>>>(pXLR, prow1, psrcf, pea,
                                          att[1], We[1], bb[1], 0,
                                          nullptr, pAhi, pAlo);
    // Layer 2
    gemm_bf16_ldsm_kernel<<<ggrid, 256, 65536>>>(pAhi, pAlo, NN, HC,
                                                 pWhi + 384 * 512, pWlo + 384 * 512,
                                                 bl[2], br[2], pXLR);
    gat_node_kernel<<<node_blocks, 256>>>(pXLR, prow1, psrcf, pea,
                                          att[2], We[2], bb[2], 0,
                                          pHA, nullptr, nullptr);
    // Classifier
    fc_kernel<<<(NN * 32 + 255) / 256, 256>>>(pHA, fcW, fcb, out);
}